// round 13
// baseline (speedup 1.0000x reference)
#include <cuda_runtime.h>
#include <cstdint>
#include <math.h>

#define BSZ 4
#define TLEN 2048
#define CDIM 1024
#define NH 16
#define HD 64
#define BT (BSZ * TLEN)      /* 8192 */
#define N3 (3 * CDIM)        /* 3072 */

// Scratch (allocation-free rule: __device__ globals)
__device__ float g_Q[BT * CDIM];      // [B,H,T,Dh]
__device__ float g_K[BT * CDIM];
__device__ float g_V[BT * CDIM];
__device__ float g_att[BT * CDIM];    // [B,T,C] (tf32-rounded bits)
__device__ float g_WqkvT[N3 * CDIM];  // [3072,1024]  (W_qkv^T, tf32-rounded)
__device__ float g_WprojT[CDIM * CDIM]; // (W_proj^T, tf32-rounded)

// ---------------------------------------------------------------------------
// Portable tensor-core helpers (sm_80+ mma.sync — no 'a'-suffix features)
// ---------------------------------------------------------------------------
__device__ __forceinline__ uint32_t f2tf32(float x) {
    uint32_t u;
    asm("cvt.rna.tf32.f32 %0, %1;" : "=r"(u) : "f"(x));
    return u;
}

#define MMA_TF32(d, a, b)                                                        \
    asm volatile(                                                                \
        "mma.sync.aligned.m16n8k8.row.col.f32.tf32.tf32.f32 "                    \
        "{%0,%1,%2,%3}, {%4,%5,%6,%7}, {%8,%9}, {%0,%1,%2,%3};"                  \
        : "+f"((d)[0]), "+f"((d)[1]), "+f"((d)[2]), "+f"((d)[3])                 \
        : "r"((a)[0]), "r"((a)[1]), "r"((a)[2]), "r"((a)[3]),                    \
          "r"((b)[0]), "r"((b)[1]))

// ---------------------------------------------------------------------------
// One-shot weight transposes + tf32 pre-round: out[N,K] = rna(in[K,N]^T).
// ---------------------------------------------------------------------------
__global__ __launch_bounds__(256) void transpose32(const float* __restrict__ in,
                                                   float* __restrict__ out,
                                                   int R, int C) {
    __shared__ float tile[32][33];
    const int c0 = blockIdx.x * 32, r0 = blockIdx.y * 32;
    const int tx = threadIdx.x & 31, ty = threadIdx.x >> 5;
#pragma unroll
    for (int i = 0; i < 4; i++) {
        int r = ty + i * 8;
        tile[r][tx] = in[(size_t)(r0 + r) * C + c0 + tx];
    }
    __syncthreads();
#pragma unroll
    for (int i = 0; i < 4; i++) {
        int r = ty + i * 8;
        out[(size_t)(c0 + r) * R + r0 + tx] =
            __uint_as_float(f2tf32(tile[tx][r]));
    }
}

// ---------------------------------------------------------------------------
// tf32 mma.sync GEMM, double-buffered smem, ONE barrier per K chunk,
// batched LDG staging (MLP=8). At legacy-tensor roofline — unchanged (R12).
// MODE 0: QKV epilogue scatter -> g_Q/g_K/g_V;  MODE 1: plain out.
// ---------------------------------------------------------------------------
#define SSTR 36
#define MMT (128 * SSTR)
#define MM_SMEM (4 * MMT * 4)

template <int MODE, bool CVT_A>
__global__ __launch_bounds__(256, 2)
void mm_tf32(const float* __restrict__ A, const float* __restrict__ Bt,
             const float* __restrict__ bias, float* __restrict__ out) {
    extern __shared__ uint32_t gsm[];   // [A0 | B0 | A1 | B1]

    const int t = threadIdx.x;
    const int m0 = blockIdx.y * 128;
    const int n0 = blockIdx.x * 128;
    const int lane = t & 31, w = t >> 5;
    const int wr = w >> 2, wc = w & 3;

    float d[4][4][4];
#pragma unroll
    for (int i = 0; i < 4; i++)
#pragma unroll
        for (int j = 0; j < 4; j++)
#pragma unroll
            for (int e = 0; e < 4; e++) d[i][j][e] = 0.f;

    const int gr = t >> 3;
    const int gc4 = (t & 7) * 4;
    const float* Ap = A + (size_t)(m0 + gr) * CDIM + gc4;
    const float* Bp = Bt + (size_t)(n0 + gr) * CDIM + gc4;

    const int ar = wr * 64 + (lane >> 2);
    const int ac = lane & 3;
    const int br = wc * 32 + (lane >> 2);

    for (int k0 = 0; k0 < CDIM; k0 += 32) {
        const int st = (k0 >> 5) & 1;
        uint32_t* As = gsm + st * 2 * MMT;
        uint32_t* Bs = As + MMT;

        float4 va[4], vb[4];
#pragma unroll
        for (int p = 0; p < 4; p++)
            va[p] = *(const float4*)(Ap + (size_t)(p * 32) * CDIM + k0);
#pragma unroll
        for (int p = 0; p < 4; p++)
            vb[p] = *(const float4*)(Bp + (size_t)(p * 32) * CDIM + k0);

#pragma unroll
        for (int p = 0; p < 4; p++) {
            const int row = gr + p * 32;
            uint4 ua;
            if (CVT_A) {
                ua.x = f2tf32(va[p].x); ua.y = f2tf32(va[p].y);
                ua.z = f2tf32(va[p].z); ua.w = f2tf32(va[p].w);
            } else {
                ua.x = __float_as_uint(va[p].x); ua.y = __float_as_uint(va[p].y);
                ua.z = __float_as_uint(va[p].z); ua.w = __float_as_uint(va[p].w);
            }
            uint4 ub;  // pre-rounded
            ub.x = __float_as_uint(vb[p].x); ub.y = __float_as_uint(vb[p].y);
            ub.z = __float_as_uint(vb[p].z); ub.w = __float_as_uint(vb[p].w);
            *(uint4*)&As[row * SSTR + gc4] = ua;
            *(uint4*)&Bs[row * SSTR + gc4] = ub;
        }
        __syncthreads();

#pragma unroll
        for (int ks = 0; ks < 4; ks++) {
            const int kk = ks * 8 + ac;
            uint32_t a[4][4], b[4][2];
#pragma unroll
            for (int i = 0; i < 4; i++) {
                const int r = (ar + i * 16) * SSTR;
                a[i][0] = As[r + kk];
                a[i][1] = As[r + 8 * SSTR + kk];
                a[i][2] = As[r + kk + 4];
                a[i][3] = As[r + 8 * SSTR + kk + 4];
            }
#pragma unroll
            for (int j = 0; j < 4; j++) {
                const int r = (br + j * 8) * SSTR;
                b[j][0] = Bs[r + kk];
                b[j][1] = Bs[r + kk + 4];
            }
#pragma unroll
            for (int i = 0; i < 4; i++)
#pragma unroll
                for (int j = 0; j < 4; j++) MMA_TF32(d[i][j], a[i], b[j]);
        }
    }

    const int r0 = lane >> 2, c0 = (lane & 3) * 2;
#pragma unroll
    for (int i = 0; i < 4; i++) {
        const int gmA = m0 + wr * 64 + i * 16 + r0;
        const int gmB = gmA + 8;
#pragma unroll
        for (int j = 0; j < 4; j++) {
            const int gn = n0 + wc * 32 + j * 8 + c0;
            const float bx = bias[gn], by = bias[gn + 1];
            float2 vA = make_float2(d[i][j][0] + bx, d[i][j][1] + by);
            float2 vB = make_float2(d[i][j][2] + bx, d[i][j][3] + by);
            if (MODE == 0) {
                const int which = gn >> 10;
                const int c = gn & 1023;
                const int h = c >> 6, d0 = c & 63;
                float* base = (which == 0) ? g_Q : ((which == 1) ? g_K : g_V);
                const int bA = gmA >> 11, tA = gmA & 2047;
                const int bB = gmB >> 11, tB = gmB & 2047;
                *(float2*)(base + ((size_t)(bA * NH + h) * TLEN + tA) * HD + d0) = vA;
                *(float2*)(base + ((size_t)(bB * NH + h) * TLEN + tB) * HD + d0) = vB;
            } else {
                *(float2*)(out + (size_t)gmA * CDIM + gn) = vA;
                *(float2*)(out + (size_t)gmB * CDIM + gn) = vB;
            }
        }
    }
}

// ---------------------------------------------------------------------------
// Tensor-core flash attention v8 (causal, tf32 mma.sync).
// CHANGES vs R12:
//  - __launch_bounds__(128, 4): cap regs at 128 -> 4 resident CTAs/SM.
//  - Diagonal-tile skip: warp w's fully-masked fragments (j or ks >= 2w+2)
//    contribute exact zeros -> MMAs skipped (bit-exact).
// ---------------------------------------------------------------------------
#define SA 68
#define ATTN_SMEM (2 * 64 * SA * 4)

__global__ __launch_bounds__(128, 4) void attn_mma() {
    extern __shared__ uint32_t smw[];
    uint32_t* Ks = smw;               // 64 x SA (also Q staging pre-loop)
    uint32_t* Vs = smw + 64 * SA;     // 64 x SA  (Vs[key][d], row-major)

    const int t = threadIdx.x;
    const int lane = t & 31, w = t >> 5;
    const int qi = (gridDim.x - 1) - blockIdx.x;  // heavy tiles first
    const int bh = blockIdx.y;
    const int q0 = qi * 64;

    const float* Qg = g_Q + (size_t)bh * TLEN * HD;
    const float* Kg = g_K + (size_t)bh * TLEN * HD;
    const float* Vg = g_V + (size_t)bh * TLEN * HD;

    const int r0w = w * 16 + (lane >> 2);
    const int abase = r0w * SA;
    const int lk = lane & 3;
    const int src0 = (lane & 28) + ((lane >> 1) & 1);
    const int src1 = src0 + 2;
    const bool oddl = lane & 1;
    const int wlim = 2 * w + 2;   // first fully-masked frag index on diag tile

    // Stage Q (batched LDGs), then hoist fragments to registers.
    {
        float4 qv[8];
#pragma unroll
        for (int it = 0; it < 8; it++) {
            const int i = it * 128 + t;
            qv[it] = *(const float4*)(Qg + (size_t)(q0 + (i >> 4)) * HD +
                                      (i & 15) * 4);
        }
#pragma unroll
        for (int it = 0; it < 8; it++) {
            const int i = it * 128 + t;
            const int row = i >> 4, c4 = (i & 15) * 4;
            uint4 u;
            u.x = f2tf32(qv[it].x * 0.125f);
            u.y = f2tf32(qv[it].y * 0.125f);
            u.z = f2tf32(qv[it].z * 0.125f);
            u.w = f2tf32(qv[it].w * 0.125f);
            *(uint4*)&Ks[row * SA + c4] = u;
        }
    }
    __syncthreads();
    uint32_t qf[8][4];
#pragma unroll
    for (int ks = 0; ks < 8; ks++) {
        const int kk = ks * 8 + lk;
        qf[ks][0] = Ks[abase + kk];
        qf[ks][1] = Ks[abase + 8 * SA + kk];
        qf[ks][2] = Ks[abase + kk + 4];
        qf[ks][3] = Ks[abase + 8 * SA + kk + 4];
    }

    float o[8][4];
#pragma unroll
    for (int j = 0; j < 8; j++)
#pragma unroll
        for (int e = 0; e < 4; e++) o[j][e] = 0.f;
    float m0 = -1e30f, m1 = -1e30f, l0 = 0.f, l1 = 0.f;

    for (int kt = 0; kt <= qi; kt++) {
        const int k0 = kt * 64;
        const bool diag = (kt == qi);
        const int jlim = diag ? wlim : 8;
        __syncthreads();  // Ks/Vs free of prior readers (incl. Q frag loads)

        // Staging, batched: two phases, each with 8 LDG.128 in flight.
#pragma unroll
        for (int half = 0; half < 2; half++) {
            float4 kr[4], vr[4];
#pragma unroll
            for (int it = 0; it < 4; it++) {
                const int i = (half * 4 + it) * 128 + t;
                const int row = i >> 4, c4 = (i & 15) * 4;
                kr[it] = *(const float4*)(Kg + (size_t)(k0 + row) * HD + c4);
                vr[it] = *(const float4*)(Vg + (size_t)(k0 + row) * HD + c4);
            }
#pragma unroll
            for (int it = 0; it < 4; it++) {
                const int i = (half * 4 + it) * 128 + t;
                const int row = i >> 4, c4 = (i & 15) * 4;
                uint4 u;
                u.x = f2tf32(kr[it].x); u.y = f2tf32(kr[it].y);
                u.z = f2tf32(kr[it].z); u.w = f2tf32(kr[it].w);
                *(uint4*)&Ks[row * SA + c4] = u;
                uint4 uv;
                uv.x = f2tf32(vr[it].x); uv.y = f2tf32(vr[it].y);
                uv.z = f2tf32(vr[it].z); uv.w = f2tf32(vr[it].w);
                *(uint4*)&Vs[row * SA + c4] = uv;
            }
        }
        __syncthreads();

        // S = (Q*scale) @ K^T   (skip fully-masked frags on diag tile)
        float s[8][4];
#pragma unroll
        for (int j = 0; j < 8; j++)
#pragma unroll
            for (int e = 0; e < 4; e++) s[j][e] = 0.f;
#pragma unroll
        for (int ks = 0; ks < 8; ks++) {
            const int kk = ks * 8 + lk;
#pragma unroll
            for (int j = 0; j < 8; j++) {
                if (j < jlim) {
                    const int r = (j * 8 + (lane >> 2)) * SA;
                    uint32_t b[2];
                    b[0] = Ks[r + kk];
                    b[1] = Ks[r + kk + 4];
                    MMA_TF32(s[j], qf[ks], b);
                }
            }
        }

        // Causal mask (diagonal tile only; uniform branch)
        if (diag) {
            const int gr0 = q0 + r0w, gr1 = gr0 + 8;
#pragma unroll
            for (int j = 0; j < 8; j++) {
                const int c = k0 + j * 8 + 2 * lk;
                if (c > gr0) s[j][0] = -1e30f;
                if (c + 1 > gr0) s[j][1] = -1e30f;
                if (c > gr1) s[j][2] = -1e30f;
                if (c + 1 > gr1) s[j][3] = -1e30f;
            }
        }

        // Online softmax: rows r0w (c0,c1) and r0w+8 (c2,c3)
        float tm0 = -1e30f, tm1 = -1e30f;
#pragma unroll
        for (int j = 0; j < 8; j++) {
            tm0 = fmaxf(tm0, fmaxf(s[j][0], s[j][1]));
            tm1 = fmaxf(tm1, fmaxf(s[j][2], s[j][3]));
        }
        tm0 = fmaxf(tm0, __shfl_xor_sync(0xffffffffu, tm0, 1));
        tm0 = fmaxf(tm0, __shfl_xor_sync(0xffffffffu, tm0, 2));
        tm1 = fmaxf(tm1, __shfl_xor_sync(0xffffffffu, tm1, 1));
        tm1 = fmaxf(tm1, __shfl_xor_sync(0xffffffffu, tm1, 2));

        const float mn0 = fmaxf(m0, tm0), mn1 = fmaxf(m1, tm1);
        const float al0 = __expf(m0 - mn0), al1 = __expf(m1 - mn1);
        m0 = mn0; m1 = mn1;

        float rs0 = 0.f, rs1 = 0.f;
#pragma unroll
        for (int j = 0; j < 8; j++) {
            s[j][0] = __expf(s[j][0] - mn0); rs0 += s[j][0];
            s[j][1] = __expf(s[j][1] - mn0); rs0 += s[j][1];
            s[j][2] = __expf(s[j][2] - mn1); rs1 += s[j][2];
            s[j][3] = __expf(s[j][3] - mn1); rs1 += s[j][3];
        }
        rs0 += __shfl_xor_sync(0xffffffffu, rs0, 1);
        rs0 += __shfl_xor_sync(0xffffffffu, rs0, 2);
        rs1 += __shfl_xor_sync(0xffffffffu, rs1, 1);
        rs1 += __shfl_xor_sync(0xffffffffu, rs1, 2);
        l0 = l0 * al0 + rs0;
        l1 = l1 * al1 + rs1;
#pragma unroll
        for (int j = 0; j < 8; j++) {
            o[j][0] *= al0; o[j][1] *= al0;
            o[j][2] *= al1; o[j][3] *= al1;
        }

        // O += P @ V  (skip fully-masked key-steps on diag tile: P == 0)
#pragma unroll
        for (int ks = 0; ks < 8; ks++) {
            if (ks < jlim) {
                float v00 = __shfl_sync(0xffffffffu, s[ks][0], src0);
                float v01 = __shfl_sync(0xffffffffu, s[ks][1], src0);
                float v20 = __shfl_sync(0xffffffffu, s[ks][2], src0);
                float v21 = __shfl_sync(0xffffffffu, s[ks][3], src0);
                float v0b = __shfl_sync(0xffffffffu, s[ks][0], src1);
                float v1b = __shfl_sync(0xffffffffu, s[ks][1], src1);
                float v2b = __shfl_sync(0xffffffffu, s[ks][2], src1);
                float v3b = __shfl_sync(0xffffffffu, s[ks][3], src1);
                uint32_t a[4];
                a[0] = f2tf32(oddl ? v01 : v00);
                a[1] = f2tf32(oddl ? v21 : v20);
                a[2] = f2tf32(oddl ? v1b : v0b);
                a[3] = f2tf32(oddl ? v3b : v2b);
                const int vr0 = (ks * 8 + lk) * SA;
                const int vr1 = (ks * 8 + lk + 4) * SA;
#pragma unroll
                for (int j = 0; j < 8; j++) {
                    const int dcol = j * 8 + (lane >> 2);
                    uint32_t b[2];
                    b[0] = Vs[vr0 + dcol];
                    b[1] = Vs[vr1 + dcol];
                    MMA_TF32(o[j], a, b);
                }
            }
        }
    }

    // Epilogue -> g_att [B,T,C], tf32 pre-rounded (proj skips its A cvt)
    const float inv0 = 1.f / l0, inv1 = 1.f / l1;
    const int b = bh >> 4, h = bh & 15;
    const int gr0 = q0 + r0w, gr1 = gr0 + 8;
    float* o0 = g_att + ((size_t)(b * TLEN + gr0)) * CDIM + h * HD;
    float* o1 = g_att + ((size_t)(b * TLEN + gr1)) * CDIM + h * HD;
#pragma unroll
    for (int j = 0; j < 8; j++) {
        const int c = j * 8 + 2 * lk;
        *(float2*)(o0 + c) = make_float2(__uint_as_float(f2tf32(o[j][0] * inv0)),
                                         __uint_as_float(f2tf32(o[j][1] * inv0)));
        *(float2*)(o1 + c) = make_float2(__uint_as_float(f2tf32(o[j][2] * inv1)),
                                         __uint_as_float(f2tf32(o[j][3] * inv1)));
    }
}

// ---------------------------------------------------------------------------
extern "C" void kernel_launch(void* const* d_in, const int* in_sizes, int n_in,
                              void* d_out, int out_size) {
    const float* x = (const float*)d_in[0];
    const float* W_qkv = (const float*)d_in[1];
    const float* b_qkv = (const float*)d_in[2];
    const float* W_proj = (const float*)d_in[3];
    const float* b_proj = (const float*)d_in[4];
    float* out = (float*)d_out;

    float *wqkvT = nullptr, *wprojT = nullptr, *attp = nullptr;
    cudaGetSymbolAddress((void**)&wqkvT, g_WqkvT);
    cudaGetSymbolAddress((void**)&wprojT, g_WprojT);
    cudaGetSymbolAddress((void**)&attp, g_att);

    cudaFuncSetAttribute(attn_mma, cudaFuncAttributeMaxDynamicSharedMemorySize,
                         ATTN_SMEM);
    cudaFuncSetAttribute(mm_tf32<0, true>,
                         cudaFuncAttributeMaxDynamicSharedMemorySize, MM_SMEM);
    cudaFuncSetAttribute(mm_tf32<1, false>,
                         cudaFuncAttributeMaxDynamicSharedMemorySize, MM_SMEM);

    transpose32<<<dim3(N3 / 32, CDIM / 32), 256>>>(W_qkv, wqkvT, CDIM, N3);
    transpose32<<<dim3(CDIM / 32, CDIM / 32), 256>>>(W_proj, wprojT, CDIM, CDIM);

    mm_tf32<0, true><<<dim3(N3 / 128, BT / 128), 256, MM_SMEM>>>(
        x, wqkvT, b_qkv, nullptr);

    attn_mma<<<dim3(TLEN / 64, BSZ * NH), 128, ATTN_SMEM>>>();

    mm_tf32<1, false><<<dim3(CDIM / 128, BT / 128), 256, MM_SMEM>>>(
        attp, wprojT, b_proj, out);
}

// round 14
// speedup vs baseline: 1.0521x; 1.0521x over previous
#include <cuda_runtime.h>
#include <cstdint>
#include <math.h>

#define BSZ 4
#define TLEN 2048
#define CDIM 1024
#define NH 16
#define HD 64
#define BT (BSZ * TLEN)      /* 8192 */
#define N3 (3 * CDIM)        /* 3072 */

// Scratch (allocation-free rule: __device__ globals)
__device__ float g_Q[BT * CDIM];      // [B,H,T,Dh]
__device__ float g_K[BT * CDIM];
__device__ float g_V[BT * CDIM];
__device__ float g_att[BT * CDIM];    // [B,T,C] (tf32-rounded bits)
__device__ float g_WqkvT[N3 * CDIM];  // [3072,1024]  (W_qkv^T, tf32-rounded)
__device__ float g_WprojT[CDIM * CDIM]; // (W_proj^T, tf32-rounded)

// ---------------------------------------------------------------------------
// Portable tensor-core helpers (sm_80+ mma.sync — no 'a'-suffix features)
// ---------------------------------------------------------------------------
__device__ __forceinline__ uint32_t f2tf32(float x) {
    uint32_t u;
    asm("cvt.rna.tf32.f32 %0, %1;" : "=r"(u) : "f"(x));
    return u;
}

#define MMA_TF32(d, a, b)                                                        \
    asm volatile(                                                                \
        "mma.sync.aligned.m16n8k8.row.col.f32.tf32.tf32.f32 "                    \
        "{%0,%1,%2,%3}, {%4,%5,%6,%7}, {%8,%9}, {%0,%1,%2,%3};"                  \
        : "+f"((d)[0]), "+f"((d)[1]), "+f"((d)[2]), "+f"((d)[3])                 \
        : "r"((a)[0]), "r"((a)[1]), "r"((a)[2]), "r"((a)[3]),                    \
          "r"((b)[0]), "r"((b)[1]))

// ---------------------------------------------------------------------------
// One-shot weight transposes + tf32 pre-round: out[N,K] = rna(in[K,N]^T).
// ---------------------------------------------------------------------------
__global__ __launch_bounds__(256) void transpose32(const float* __restrict__ in,
                                                   float* __restrict__ out,
                                                   int R, int C) {
    __shared__ float tile[32][33];
    const int c0 = blockIdx.x * 32, r0 = blockIdx.y * 32;
    const int tx = threadIdx.x & 31, ty = threadIdx.x >> 5;
#pragma unroll
    for (int i = 0; i < 4; i++) {
        int r = ty + i * 8;
        tile[r][tx] = in[(size_t)(r0 + r) * C + c0 + tx];
    }
    __syncthreads();
#pragma unroll
    for (int i = 0; i < 4; i++) {
        int r = ty + i * 8;
        out[(size_t)(c0 + r) * R + r0 + tx] =
            __uint_as_float(f2tf32(tile[tx][r]));
    }
}

// ---------------------------------------------------------------------------
// tf32 mma.sync GEMM, double-buffered smem, ONE barrier per K chunk,
// batched LDG staging (MLP=8). At legacy-tensor roofline — unchanged (R12).
// MODE 0: QKV epilogue scatter -> g_Q/g_K/g_V;  MODE 1: plain out.
// ---------------------------------------------------------------------------
#define SSTR 36
#define MMT (128 * SSTR)
#define MM_SMEM (4 * MMT * 4)

template <int MODE, bool CVT_A>
__global__ __launch_bounds__(256, 2)
void mm_tf32(const float* __restrict__ A, const float* __restrict__ Bt,
             const float* __restrict__ bias, float* __restrict__ out) {
    extern __shared__ uint32_t gsm[];   // [A0 | B0 | A1 | B1]

    const int t = threadIdx.x;
    const int m0 = blockIdx.y * 128;
    const int n0 = blockIdx.x * 128;
    const int lane = t & 31, w = t >> 5;
    const int wr = w >> 2, wc = w & 3;

    float d[4][4][4];
#pragma unroll
    for (int i = 0; i < 4; i++)
#pragma unroll
        for (int j = 0; j < 4; j++)
#pragma unroll
            for (int e = 0; e < 4; e++) d[i][j][e] = 0.f;

    const int gr = t >> 3;
    const int gc4 = (t & 7) * 4;
    const float* Ap = A + (size_t)(m0 + gr) * CDIM + gc4;
    const float* Bp = Bt + (size_t)(n0 + gr) * CDIM + gc4;

    const int ar = wr * 64 + (lane >> 2);
    const int ac = lane & 3;
    const int br = wc * 32 + (lane >> 2);

    for (int k0 = 0; k0 < CDIM; k0 += 32) {
        const int st = (k0 >> 5) & 1;
        uint32_t* As = gsm + st * 2 * MMT;
        uint32_t* Bs = As + MMT;

        float4 va[4], vb[4];
#pragma unroll
        for (int p = 0; p < 4; p++)
            va[p] = *(const float4*)(Ap + (size_t)(p * 32) * CDIM + k0);
#pragma unroll
        for (int p = 0; p < 4; p++)
            vb[p] = *(const float4*)(Bp + (size_t)(p * 32) * CDIM + k0);

#pragma unroll
        for (int p = 0; p < 4; p++) {
            const int row = gr + p * 32;
            uint4 ua;
            if (CVT_A) {
                ua.x = f2tf32(va[p].x); ua.y = f2tf32(va[p].y);
                ua.z = f2tf32(va[p].z); ua.w = f2tf32(va[p].w);
            } else {
                ua.x = __float_as_uint(va[p].x); ua.y = __float_as_uint(va[p].y);
                ua.z = __float_as_uint(va[p].z); ua.w = __float_as_uint(va[p].w);
            }
            uint4 ub;  // pre-rounded
            ub.x = __float_as_uint(vb[p].x); ub.y = __float_as_uint(vb[p].y);
            ub.z = __float_as_uint(vb[p].z); ub.w = __float_as_uint(vb[p].w);
            *(uint4*)&As[row * SSTR + gc4] = ua;
            *(uint4*)&Bs[row * SSTR + gc4] = ub;
        }
        __syncthreads();

#pragma unroll
        for (int ks = 0; ks < 4; ks++) {
            const int kk = ks * 8 + ac;
            uint32_t a[4][4], b[4][2];
#pragma unroll
            for (int i = 0; i < 4; i++) {
                const int r = (ar + i * 16) * SSTR;
                a[i][0] = As[r + kk];
                a[i][1] = As[r + 8 * SSTR + kk];
                a[i][2] = As[r + kk + 4];
                a[i][3] = As[r + 8 * SSTR + kk + 4];
            }
#pragma unroll
            for (int j = 0; j < 4; j++) {
                const int r = (br + j * 8) * SSTR;
                b[j][0] = Bs[r + kk];
                b[j][1] = Bs[r + kk + 4];
            }
#pragma unroll
            for (int i = 0; i < 4; i++)
#pragma unroll
                for (int j = 0; j < 4; j++) MMA_TF32(d[i][j], a[i], b[j]);
        }
    }

    const int r0 = lane >> 2, c0 = (lane & 3) * 2;
#pragma unroll
    for (int i = 0; i < 4; i++) {
        const int gmA = m0 + wr * 64 + i * 16 + r0;
        const int gmB = gmA + 8;
#pragma unroll
        for (int j = 0; j < 4; j++) {
            const int gn = n0 + wc * 32 + j * 8 + c0;
            const float bx = bias[gn], by = bias[gn + 1];
            float2 vA = make_float2(d[i][j][0] + bx, d[i][j][1] + by);
            float2 vB = make_float2(d[i][j][2] + bx, d[i][j][3] + by);
            if (MODE == 0) {
                const int which = gn >> 10;
                const int c = gn & 1023;
                const int h = c >> 6, d0 = c & 63;
                float* base = (which == 0) ? g_Q : ((which == 1) ? g_K : g_V);
                const int bA = gmA >> 11, tA = gmA & 2047;
                const int bB = gmB >> 11, tB = gmB & 2047;
                *(float2*)(base + ((size_t)(bA * NH + h) * TLEN + tA) * HD + d0) = vA;
                *(float2*)(base + ((size_t)(bB * NH + h) * TLEN + tB) * HD + d0) = vB;
            } else {
                *(float2*)(out + (size_t)gmA * CDIM + gn) = vA;
                *(float2*)(out + (size_t)gmB * CDIM + gn) = vB;
            }
        }
    }
}

// ---------------------------------------------------------------------------
// Tensor-core flash attention v9 (causal, tf32 mma.sync).
// R12 structure EXACTLY (no reg cap — batched staging needs ~157 regs), plus
// ONLY the diagonal-tile skip: warp w's fully-masked fragments (j/ks >= 2w+2)
// contribute exact zeros -> their MMAs and shfl/cvt work skipped (bit-exact).
// ---------------------------------------------------------------------------
#define SA 68
#define ATTN_SMEM (2 * 64 * SA * 4)

__global__ __launch_bounds__(128) void attn_mma() {
    extern __shared__ uint32_t smw[];
    uint32_t* Ks = smw;               // 64 x SA (also Q staging pre-loop)
    uint32_t* Vs = smw + 64 * SA;     // 64 x SA  (Vs[key][d], row-major)

    const int t = threadIdx.x;
    const int lane = t & 31, w = t >> 5;
    const int qi = (gridDim.x - 1) - blockIdx.x;  // heavy tiles first
    const int bh = blockIdx.y;
    const int q0 = qi * 64;

    const float* Qg = g_Q + (size_t)bh * TLEN * HD;
    const float* Kg = g_K + (size_t)bh * TLEN * HD;
    const float* Vg = g_V + (size_t)bh * TLEN * HD;

    const int r0w = w * 16 + (lane >> 2);
    const int abase = r0w * SA;
    const int lk = lane & 3;
    const int src0 = (lane & 28) + ((lane >> 1) & 1);
    const int src1 = src0 + 2;
    const bool oddl = lane & 1;
    const int wlim = 2 * w + 2;   // first fully-masked frag index on diag tile

    // Stage Q (batched: 8 LDG.128 in flight), then hoist frags to registers.
    {
        float4 qv[8];
#pragma unroll
        for (int it = 0; it < 8; it++) {
            const int i = it * 128 + t;
            qv[it] = *(const float4*)(Qg + (size_t)(q0 + (i >> 4)) * HD +
                                      (i & 15) * 4);
        }
#pragma unroll
        for (int it = 0; it < 8; it++) {
            const int i = it * 128 + t;
            const int row = i >> 4, c4 = (i & 15) * 4;
            uint4 u;
            u.x = f2tf32(qv[it].x * 0.125f);
            u.y = f2tf32(qv[it].y * 0.125f);
            u.z = f2tf32(qv[it].z * 0.125f);
            u.w = f2tf32(qv[it].w * 0.125f);
            *(uint4*)&Ks[row * SA + c4] = u;
        }
    }
    __syncthreads();
    uint32_t qf[8][4];
#pragma unroll
    for (int ks = 0; ks < 8; ks++) {
        const int kk = ks * 8 + lk;
        qf[ks][0] = Ks[abase + kk];
        qf[ks][1] = Ks[abase + 8 * SA + kk];
        qf[ks][2] = Ks[abase + kk + 4];
        qf[ks][3] = Ks[abase + 8 * SA + kk + 4];
    }

    float o[8][4];
#pragma unroll
    for (int j = 0; j < 8; j++)
#pragma unroll
        for (int e = 0; e < 4; e++) o[j][e] = 0.f;
    float m0 = -1e30f, m1 = -1e30f, l0 = 0.f, l1 = 0.f;

    for (int kt = 0; kt <= qi; kt++) {
        const int k0 = kt * 64;
        const bool diag = (kt == qi);
        const int jlim = diag ? wlim : 8;
        __syncthreads();  // Ks/Vs free of prior readers (incl. Q frag loads)

        // Staging, batched: two phases, each with 8 LDG.128 in flight.
#pragma unroll
        for (int half = 0; half < 2; half++) {
            float4 kr[4], vr[4];
#pragma unroll
            for (int it = 0; it < 4; it++) {
                const int i = (half * 4 + it) * 128 + t;
                const int row = i >> 4, c4 = (i & 15) * 4;
                kr[it] = *(const float4*)(Kg + (size_t)(k0 + row) * HD + c4);
                vr[it] = *(const float4*)(Vg + (size_t)(k0 + row) * HD + c4);
            }
#pragma unroll
            for (int it = 0; it < 4; it++) {
                const int i = (half * 4 + it) * 128 + t;
                const int row = i >> 4, c4 = (i & 15) * 4;
                uint4 u;
                u.x = f2tf32(kr[it].x); u.y = f2tf32(kr[it].y);
                u.z = f2tf32(kr[it].z); u.w = f2tf32(kr[it].w);
                *(uint4*)&Ks[row * SA + c4] = u;
                uint4 uv;
                uv.x = f2tf32(vr[it].x); uv.y = f2tf32(vr[it].y);
                uv.z = f2tf32(vr[it].z); uv.w = f2tf32(vr[it].w);
                *(uint4*)&Vs[row * SA + c4] = uv;
            }
        }
        __syncthreads();

        // S = (Q*scale) @ K^T   (skip fully-masked frags on diag tile)
        float s[8][4];
#pragma unroll
        for (int j = 0; j < 8; j++)
#pragma unroll
            for (int e = 0; e < 4; e++) s[j][e] = 0.f;
#pragma unroll
        for (int ks = 0; ks < 8; ks++) {
            const int kk = ks * 8 + lk;
#pragma unroll
            for (int j = 0; j < 8; j++) {
                if (j < jlim) {
                    const int r = (j * 8 + (lane >> 2)) * SA;
                    uint32_t b[2];
                    b[0] = Ks[r + kk];
                    b[1] = Ks[r + kk + 4];
                    MMA_TF32(s[j], qf[ks], b);
                }
            }
        }

        // Causal mask (diagonal tile only; uniform branch)
        if (diag) {
            const int gr0 = q0 + r0w, gr1 = gr0 + 8;
#pragma unroll
            for (int j = 0; j < 8; j++) {
                const int c = k0 + j * 8 + 2 * lk;
                if (c > gr0) s[j][0] = -1e30f;
                if (c + 1 > gr0) s[j][1] = -1e30f;
                if (c > gr1) s[j][2] = -1e30f;
                if (c + 1 > gr1) s[j][3] = -1e30f;
            }
        }

        // Online softmax: rows r0w (c0,c1) and r0w+8 (c2,c3)
        float tm0 = -1e30f, tm1 = -1e30f;
#pragma unroll
        for (int j = 0; j < 8; j++) {
            tm0 = fmaxf(tm0, fmaxf(s[j][0], s[j][1]));
            tm1 = fmaxf(tm1, fmaxf(s[j][2], s[j][3]));
        }
        tm0 = fmaxf(tm0, __shfl_xor_sync(0xffffffffu, tm0, 1));
        tm0 = fmaxf(tm0, __shfl_xor_sync(0xffffffffu, tm0, 2));
        tm1 = fmaxf(tm1, __shfl_xor_sync(0xffffffffu, tm1, 1));
        tm1 = fmaxf(tm1, __shfl_xor_sync(0xffffffffu, tm1, 2));

        const float mn0 = fmaxf(m0, tm0), mn1 = fmaxf(m1, tm1);
        const float al0 = __expf(m0 - mn0), al1 = __expf(m1 - mn1);
        m0 = mn0; m1 = mn1;

        float rs0 = 0.f, rs1 = 0.f;
#pragma unroll
        for (int j = 0; j < 8; j++) {
            s[j][0] = __expf(s[j][0] - mn0); rs0 += s[j][0];
            s[j][1] = __expf(s[j][1] - mn0); rs0 += s[j][1];
            s[j][2] = __expf(s[j][2] - mn1); rs1 += s[j][2];
            s[j][3] = __expf(s[j][3] - mn1); rs1 += s[j][3];
        }
        rs0 += __shfl_xor_sync(0xffffffffu, rs0, 1);
        rs0 += __shfl_xor_sync(0xffffffffu, rs0, 2);
        rs1 += __shfl_xor_sync(0xffffffffu, rs1, 1);
        rs1 += __shfl_xor_sync(0xffffffffu, rs1, 2);
        l0 = l0 * al0 + rs0;
        l1 = l1 * al1 + rs1;
#pragma unroll
        for (int j = 0; j < 8; j++) {
            o[j][0] *= al0; o[j][1] *= al0;
            o[j][2] *= al1; o[j][3] *= al1;
        }

        // O += P @ V  (skip fully-masked key-steps on diag tile: P == 0)
#pragma unroll
        for (int ks = 0; ks < 8; ks++) {
            if (ks < jlim) {
                float v00 = __shfl_sync(0xffffffffu, s[ks][0], src0);
                float v01 = __shfl_sync(0xffffffffu, s[ks][1], src0);
                float v20 = __shfl_sync(0xffffffffu, s[ks][2], src0);
                float v21 = __shfl_sync(0xffffffffu, s[ks][3], src0);
                float v0b = __shfl_sync(0xffffffffu, s[ks][0], src1);
                float v1b = __shfl_sync(0xffffffffu, s[ks][1], src1);
                float v2b = __shfl_sync(0xffffffffu, s[ks][2], src1);
                float v3b = __shfl_sync(0xffffffffu, s[ks][3], src1);
                uint32_t a[4];
                a[0] = f2tf32(oddl ? v01 : v00);
                a[1] = f2tf32(oddl ? v21 : v20);
                a[2] = f2tf32(oddl ? v1b : v0b);
                a[3] = f2tf32(oddl ? v3b : v2b);
                const int vr0 = (ks * 8 + lk) * SA;
                const int vr1 = (ks * 8 + lk + 4) * SA;
#pragma unroll
                for (int j = 0; j < 8; j++) {
                    const int dcol = j * 8 + (lane >> 2);
                    uint32_t b[2];
                    b[0] = Vs[vr0 + dcol];
                    b[1] = Vs[vr1 + dcol];
                    MMA_TF32(o[j], a, b);
                }
            }
        }
    }

    // Epilogue -> g_att [B,T,C], tf32 pre-rounded (proj skips its A cvt)
    const float inv0 = 1.f / l0, inv1 = 1.f / l1;
    const int b = bh >> 4, h = bh & 15;
    const int gr0 = q0 + r0w, gr1 = gr0 + 8;
    float* o0 = g_att + ((size_t)(b * TLEN + gr0)) * CDIM + h * HD;
    float* o1 = g_att + ((size_t)(b * TLEN + gr1)) * CDIM + h * HD;
#pragma unroll
    for (int j = 0; j < 8; j++) {
        const int c = j * 8 + 2 * lk;
        *(float2*)(o0 + c) = make_float2(__uint_as_float(f2tf32(o[j][0] * inv0)),
                                         __uint_as_float(f2tf32(o[j][1] * inv0)));
        *(float2*)(o1 + c) = make_float2(__uint_as_float(f2tf32(o[j][2] * inv1)),
                                         __uint_as_float(f2tf32(o[j][3] * inv1)));
    }
}

// ---------------------------------------------------------------------------
extern "C" void kernel_launch(void* const* d_in, const int* in_sizes, int n_in,
                              void* d_out, int out_size) {
    const float* x = (const float*)d_in[0];
    const float* W_qkv = (const float*)d_in[1];
    const float* b_qkv = (const float*)d_in[2];
    const float* W_proj = (const float*)d_in[3];
    const float* b_proj = (const float*)d_in[4];
    float* out = (float*)d_out;

    float *wqkvT = nullptr, *wprojT = nullptr, *attp = nullptr;
    cudaGetSymbolAddress((void**)&wqkvT, g_WqkvT);
    cudaGetSymbolAddress((void**)&wprojT, g_WprojT);
    cudaGetSymbolAddress((void**)&attp, g_att);

    cudaFuncSetAttribute(attn_mma, cudaFuncAttributeMaxDynamicSharedMemorySize,
                         ATTN_SMEM);
    cudaFuncSetAttribute(mm_tf32<0, true>,
                         cudaFuncAttributeMaxDynamicSharedMemorySize, MM_SMEM);
    cudaFuncSetAttribute(mm_tf32<1, false>,
                         cudaFuncAttributeMaxDynamicSharedMemorySize, MM_SMEM);

    transpose32<<<dim3(N3 / 32, CDIM / 32), 256>>>(W_qkv, wqkvT, CDIM, N3);
    transpose32<<<dim3(CDIM / 32, CDIM / 32), 256>>>(W_proj, wprojT, CDIM, CDIM);

    mm_tf32<0, true><<<dim3(N3 / 128, BT / 128), 256, MM_SMEM>>>(
        x, wqkvT, b_qkv, nullptr);

    attn_mma<<<dim3(TLEN / 64, BSZ * NH), 128, ATTN_SMEM>>>();

    mm_tf32<1, false><<<dim3(CDIM / 128, BT / 128), 256, MM_SMEM>>>(
        attp, wprojT, b_proj, out);
}

// round 15
// speedup vs baseline: 1.1223x; 1.0667x over previous
#include <cuda_runtime.h>
#include <cstdint>
#include <math.h>

#define BSZ 4
#define TLEN 2048
#define CDIM 1024
#define NH 16
#define HD 64
#define BT (BSZ * TLEN)      /* 8192 */
#define N3 (3 * CDIM)        /* 3072 */

// Scratch (allocation-free rule: __device__ globals)
__device__ float g_xr[BT * CDIM];     // x, tf32-rounded bits
__device__ float g_Q[BT * CDIM];      // [B,H,T,Dh] tf32-rounded
__device__ float g_K[BT * CDIM];      // tf32-rounded
__device__ float g_V[BT * CDIM];      // tf32-rounded
__device__ float g_att[BT * CDIM];    // [B,T,C] tf32-rounded
__device__ float g_WqkvT[N3 * CDIM];  // W_qkv^T, tf32-rounded
__device__ float g_WprojT[CDIM * CDIM]; // W_proj^T, tf32-rounded

// ---------------------------------------------------------------------------
// Portable helpers (sm_80+ — no 'a'-suffix features)
// ---------------------------------------------------------------------------
__device__ __forceinline__ uint32_t f2tf32(float x) {
    uint32_t u;
    asm("cvt.rna.tf32.f32 %0, %1;" : "=r"(u) : "f"(x));
    return u;
}
__device__ __forceinline__ uint32_t smem_u32(const void* p) {
    uint32_t a;
    asm("{ .reg .u64 t; cvta.to.shared.u64 t, %1; cvt.u32.u64 %0, t; }"
        : "=r"(a) : "l"(p));
    return a;
}

#define MMA_TF32(d, a, b)                                                        \
    asm volatile(                                                                \
        "mma.sync.aligned.m16n8k8.row.col.f32.tf32.tf32.f32 "                    \
        "{%0,%1,%2,%3}, {%4,%5,%6,%7}, {%8,%9}, {%0,%1,%2,%3};"                  \
        : "+f"((d)[0]), "+f"((d)[1]), "+f"((d)[2]), "+f"((d)[3])                 \
        : "r"((a)[0]), "r"((a)[1]), "r"((a)[2]), "r"((a)[3]),                    \
          "r"((b)[0]), "r"((b)[1]))

#define CP_ASYNC16(smaddr, gptr)                                                 \
    asm volatile("cp.async.cg.shared.global [%0], [%1], 16;"                     \
                 :: "r"(smaddr), "l"(gptr))
#define CP_COMMIT()   asm volatile("cp.async.commit_group;" ::: "memory")
#define CP_WAIT_ALL() asm volatile("cp.async.wait_group 0;" ::: "memory")

// ---------------------------------------------------------------------------
// One-shot input pre-round: out[i] = rna(in[i])  (tf32 bits in fp32 storage)
// ---------------------------------------------------------------------------
__global__ __launch_bounds__(256) void round_x(const float* __restrict__ in,
                                               float* __restrict__ out, int n4) {
    const int stride = gridDim.x * blockDim.x;
    for (int i = blockIdx.x * blockDim.x + threadIdx.x; i < n4; i += stride) {
        float4 v = ((const float4*)in)[i];
        uint4 u;
        u.x = f2tf32(v.x); u.y = f2tf32(v.y);
        u.z = f2tf32(v.z); u.w = f2tf32(v.w);
        ((uint4*)out)[i] = u;
    }
}

// ---------------------------------------------------------------------------
// One-shot weight transposes + tf32 pre-round: out[N,K] = rna(in[K,N]^T).
// ---------------------------------------------------------------------------
__global__ __launch_bounds__(256) void transpose32(const float* __restrict__ in,
                                                   float* __restrict__ out,
                                                   int R, int C) {
    __shared__ float tile[32][33];
    const int c0 = blockIdx.x * 32, r0 = blockIdx.y * 32;
    const int tx = threadIdx.x & 31, ty = threadIdx.x >> 5;
#pragma unroll
    for (int i = 0; i < 4; i++) {
        int r = ty + i * 8;
        tile[r][tx] = in[(size_t)(r0 + r) * C + c0 + tx];
    }
    __syncthreads();
#pragma unroll
    for (int i = 0; i < 4; i++) {
        int r = ty + i * 8;
        out[(size_t)(c0 + r) * R + r0 + tx] =
            __uint_as_float(f2tf32(tile[tx][r]));
    }
}

// ---------------------------------------------------------------------------
// tf32 mma.sync GEMM, cp.async 2-stage pipeline, ONE barrier per K chunk.
// All inputs pre-rounded -> staging is a pure async copy; chunk k+1's loads
// overlap compute(k). MODE 0: QKV scatter (rounded); MODE 1: plain out.
// ---------------------------------------------------------------------------
#define SSTR 36
#define MMT (128 * SSTR)
#define MM_SMEM (4 * MMT * 4)

template <int MODE>
__global__ __launch_bounds__(256, 2)
void mm_tf32(const float* __restrict__ A, const float* __restrict__ Bt,
             const float* __restrict__ bias, float* __restrict__ out) {
    extern __shared__ uint32_t gsm[];   // [A0 | B0 | A1 | B1]
    const uint32_t smb = smem_u32(gsm);

    const int t = threadIdx.x;
    const int m0 = blockIdx.y * 128;
    const int n0 = blockIdx.x * 128;
    const int lane = t & 31, w = t >> 5;
    const int wr = w >> 2, wc = w & 3;

    float d[4][4][4];
#pragma unroll
    for (int i = 0; i < 4; i++)
#pragma unroll
        for (int j = 0; j < 4; j++)
#pragma unroll
            for (int e = 0; e < 4; e++) d[i][j][e] = 0.f;

    const int gr = t >> 3;
    const int gc4 = (t & 7) * 4;
    const float* Ap = A + (size_t)(m0 + gr) * CDIM + gc4;
    const float* Bp = Bt + (size_t)(n0 + gr) * CDIM + gc4;

    const int ar = wr * 64 + (lane >> 2);
    const int ac = lane & 3;
    const int br = wc * 32 + (lane >> 2);

#define MMISS(ch)                                                                \
    do {                                                                         \
        const int _k0 = (ch) * 32, _st = (ch) & 1;                               \
        const uint32_t _ab = smb + (_st ? 2u * MMT : 0u) * 4u;                   \
        const uint32_t _bb = smb + (_st ? 3u * MMT : (uint32_t)MMT) * 4u;        \
        _Pragma("unroll")                                                        \
        for (int p = 0; p < 4; p++) {                                            \
            const uint32_t off = ((gr + p * 32) * SSTR + gc4) * 4u;              \
            CP_ASYNC16(_ab + off, Ap + (size_t)(p * 32) * CDIM + _k0);           \
            CP_ASYNC16(_bb + off, Bp + (size_t)(p * 32) * CDIM + _k0);           \
        }                                                                        \
        CP_COMMIT();                                                             \
    } while (0)

    MMISS(0);

    for (int ch = 0; ch < 32; ch++) {
        uint32_t* As = gsm + (ch & 1) * 2 * MMT;
        uint32_t* Bs = As + MMT;

        CP_WAIT_ALL();        // chunk ch arrived
        __syncthreads();      // + all warps finished compute(ch-1)
        if (ch < 31) MMISS(ch + 1);  // overlaps compute(ch)

#pragma unroll
        for (int ks = 0; ks < 4; ks++) {
            const int kk = ks * 8 + ac;
            uint32_t a[4][4], b[4][2];
#pragma unroll
            for (int i = 0; i < 4; i++) {
                const int r = (ar + i * 16) * SSTR;
                a[i][0] = As[r + kk];
                a[i][1] = As[r + 8 * SSTR + kk];
                a[i][2] = As[r + kk + 4];
                a[i][3] = As[r + 8 * SSTR + kk + 4];
            }
#pragma unroll
            for (int j = 0; j < 4; j++) {
                const int r = (br + j * 8) * SSTR;
                b[j][0] = Bs[r + kk];
                b[j][1] = Bs[r + kk + 4];
            }
#pragma unroll
            for (int i = 0; i < 4; i++)
#pragma unroll
                for (int j = 0; j < 4; j++) MMA_TF32(d[i][j], a[i], b[j]);
        }
    }
#undef MMISS

    const int r0 = lane >> 2, c0 = (lane & 3) * 2;
#pragma unroll
    for (int i = 0; i < 4; i++) {
        const int gmA = m0 + wr * 64 + i * 16 + r0;
        const int gmB = gmA + 8;
#pragma unroll
        for (int j = 0; j < 4; j++) {
            const int gn = n0 + wc * 32 + j * 8 + c0;
            const float bx = bias[gn], by = bias[gn + 1];
            if (MODE == 0) {
                // Q/K/V stored tf32-rounded (attn stages with no cvt)
                float2 vA = make_float2(
                    __uint_as_float(f2tf32(d[i][j][0] + bx)),
                    __uint_as_float(f2tf32(d[i][j][1] + by)));
                float2 vB = make_float2(
                    __uint_as_float(f2tf32(d[i][j][2] + bx)),
                    __uint_as_float(f2tf32(d[i][j][3] + by)));
                const int which = gn >> 10;
                const int c = gn & 1023;
                const int h = c >> 6, d0 = c & 63;
                float* base = (which == 0) ? g_Q : ((which == 1) ? g_K : g_V);
                const int bA = gmA >> 11, tA = gmA & 2047;
                const int bB = gmB >> 11, tB = gmB & 2047;
                *(float2*)(base + ((size_t)(bA * NH + h) * TLEN + tA) * HD + d0) = vA;
                *(float2*)(base + ((size_t)(bB * NH + h) * TLEN + tB) * HD + d0) = vB;
            } else {
                float2 vA = make_float2(d[i][j][0] + bx, d[i][j][1] + by);
                float2 vB = make_float2(d[i][j][2] + bx, d[i][j][3] + by);
                *(float2*)(out + (size_t)gmA * CDIM + gn) = vA;
                *(float2*)(out + (size_t)gmB * CDIM + gn) = vB;
            }
        }
    }
}

// ---------------------------------------------------------------------------
// Tensor-core flash attention v10 (causal, tf32 mma.sync).
// K/V pre-rounded -> staging is pure cp.async (2-stage: Ks0/Ks1, Vs0/Vs1);
// tile kt+1's loads overlap compute(kt); ONE barrier per tile.
// Q frags in registers (Q pre-rounded; 0.125 scale is exact). No diag skip.
// ---------------------------------------------------------------------------
#define SA 68
#define ATILE (64 * SA)
#define ATTN_SMEM (4 * ATILE * 4)

__global__ __launch_bounds__(128) void attn_mma() {
    extern __shared__ uint32_t smw[];   // [Ks0 | Ks1 | Vs0 | Vs1]
    const uint32_t smb = smem_u32(smw);

    const int t = threadIdx.x;
    const int lane = t & 31, w = t >> 5;
    const int qi = (gridDim.x - 1) - blockIdx.x;  // heavy tiles first
    const int bh = blockIdx.y;
    const int q0 = qi * 64;

    const float* Qg = g_Q + (size_t)bh * TLEN * HD;
    const float* Kg = g_K + (size_t)bh * TLEN * HD;
    const float* Vg = g_V + (size_t)bh * TLEN * HD;

    const int r0w = w * 16 + (lane >> 2);
    const int abase = r0w * SA;
    const int lk = lane & 3;
    const int src0 = (lane & 28) + ((lane >> 1) & 1);
    const int src1 = src0 + 2;
    const bool oddl = lane & 1;

#define KV_ISSUE(kt)                                                             \
    do {                                                                         \
        const int _k0 = (kt) * 64, _st = (kt) & 1;                               \
        const uint32_t _kb = smb + (_st ? (uint32_t)ATILE : 0u) * 4u;            \
        const uint32_t _vb = smb + ((_st ? 3u : 2u) * ATILE) * 4u;               \
        _Pragma("unroll")                                                        \
        for (int it = 0; it < 8; it++) {                                         \
            const int i = it * 128 + t;                                          \
            const int row = i >> 4, c4 = (i & 15) * 4;                           \
            const uint32_t off = (row * SA + c4) * 4u;                           \
            CP_ASYNC16(_kb + off, Kg + (size_t)(_k0 + row) * HD + c4);           \
            CP_ASYNC16(_vb + off, Vg + (size_t)(_k0 + row) * HD + c4);           \
        }                                                                        \
        CP_COMMIT();                                                             \
    } while (0)

    KV_ISSUE(0);   // tile 0 -> stage 0, in flight during Q staging

    // Stage Q through Ks stage-1 buffer (free until tile 1 is issued, which
    // happens after the kt=0 barrier, i.e. after all qf loads).
    {
        uint32_t* Qs = smw + ATILE;
        float4 qv[8];
#pragma unroll
        for (int it = 0; it < 8; it++) {
            const int i = it * 128 + t;
            qv[it] = *(const float4*)(Qg + (size_t)(q0 + (i >> 4)) * HD +
                                      (i & 15) * 4);
        }
#pragma unroll
        for (int it = 0; it < 8; it++) {
            const int i = it * 128 + t;
            const int row = i >> 4, c4 = (i & 15) * 4;
            uint4 u;  // Q pre-rounded; *0.125 (2^-3) is exact
            u.x = __float_as_uint(qv[it].x * 0.125f);
            u.y = __float_as_uint(qv[it].y * 0.125f);
            u.z = __float_as_uint(qv[it].z * 0.125f);
            u.w = __float_as_uint(qv[it].w * 0.125f);
            *(uint4*)&Qs[row * SA + c4] = u;
        }
    }
    __syncthreads();
    uint32_t qf[8][4];
    {
        uint32_t* Qs = smw + ATILE;
#pragma unroll
        for (int ks = 0; ks < 8; ks++) {
            const int kk = ks * 8 + lk;
            qf[ks][0] = Qs[abase + kk];
            qf[ks][1] = Qs[abase + 8 * SA + kk];
            qf[ks][2] = Qs[abase + kk + 4];
            qf[ks][3] = Qs[abase + 8 * SA + kk + 4];
        }
    }

    float o[8][4];
#pragma unroll
    for (int j = 0; j < 8; j++)
#pragma unroll
        for (int e = 0; e < 4; e++) o[j][e] = 0.f;
    float m0 = -1e30f, m1 = -1e30f, l0 = 0.f, l1 = 0.f;

    for (int kt = 0; kt <= qi; kt++) {
        const int k0 = kt * 64;
        uint32_t* cK = smw + (kt & 1) * ATILE;
        uint32_t* cV = smw + (2 + (kt & 1)) * ATILE;

        CP_WAIT_ALL();        // tile kt arrived
        __syncthreads();      // + qf loads done (kt=0) / compute(kt-1) done
        if (kt < qi) KV_ISSUE(kt + 1);   // overlaps compute(kt)

        // S = (Q*scale) @ K^T   (Q from registers)
        float s[8][4];
#pragma unroll
        for (int j = 0; j < 8; j++)
#pragma unroll
            for (int e = 0; e < 4; e++) s[j][e] = 0.f;
#pragma unroll
        for (int ks = 0; ks < 8; ks++) {
            const int kk = ks * 8 + lk;
#pragma unroll
            for (int j = 0; j < 8; j++) {
                const int r = (j * 8 + (lane >> 2)) * SA;
                uint32_t b[2];
                b[0] = cK[r + kk];
                b[1] = cK[r + kk + 4];
                MMA_TF32(s[j], qf[ks], b);
            }
        }

        // Causal mask (diagonal tile only; uniform branch)
        if (kt == qi) {
            const int gr0 = q0 + r0w, gr1 = gr0 + 8;
#pragma unroll
            for (int j = 0; j < 8; j++) {
                const int c = k0 + j * 8 + 2 * lk;
                if (c > gr0) s[j][0] = -1e30f;
                if (c + 1 > gr0) s[j][1] = -1e30f;
                if (c > gr1) s[j][2] = -1e30f;
                if (c + 1 > gr1) s[j][3] = -1e30f;
            }
        }

        // Online softmax: rows r0w (c0,c1) and r0w+8 (c2,c3)
        float tm0 = -1e30f, tm1 = -1e30f;
#pragma unroll
        for (int j = 0; j < 8; j++) {
            tm0 = fmaxf(tm0, fmaxf(s[j][0], s[j][1]));
            tm1 = fmaxf(tm1, fmaxf(s[j][2], s[j][3]));
        }
        tm0 = fmaxf(tm0, __shfl_xor_sync(0xffffffffu, tm0, 1));
        tm0 = fmaxf(tm0, __shfl_xor_sync(0xffffffffu, tm0, 2));
        tm1 = fmaxf(tm1, __shfl_xor_sync(0xffffffffu, tm1, 1));
        tm1 = fmaxf(tm1, __shfl_xor_sync(0xffffffffu, tm1, 2));

        const float mn0 = fmaxf(m0, tm0), mn1 = fmaxf(m1, tm1);
        const float al0 = __expf(m0 - mn0), al1 = __expf(m1 - mn1);
        m0 = mn0; m1 = mn1;

        float rs0 = 0.f, rs1 = 0.f;
#pragma unroll
        for (int j = 0; j < 8; j++) {
            s[j][0] = __expf(s[j][0] - mn0); rs0 += s[j][0];
            s[j][1] = __expf(s[j][1] - mn0); rs0 += s[j][1];
            s[j][2] = __expf(s[j][2] - mn1); rs1 += s[j][2];
            s[j][3] = __expf(s[j][3] - mn1); rs1 += s[j][3];
        }
        rs0 += __shfl_xor_sync(0xffffffffu, rs0, 1);
        rs0 += __shfl_xor_sync(0xffffffffu, rs0, 2);
        rs1 += __shfl_xor_sync(0xffffffffu, rs1, 1);
        rs1 += __shfl_xor_sync(0xffffffffu, rs1, 2);
        l0 = l0 * al0 + rs0;
        l1 = l1 * al1 + rs1;
#pragma unroll
        for (int j = 0; j < 8; j++) {
            o[j][0] *= al0; o[j][1] *= al0;
            o[j][2] *= al1; o[j][3] *= al1;
        }

        // O += P @ V. P A-frags from s C-frags via in-register permute.
#pragma unroll
        for (int ks = 0; ks < 8; ks++) {
            float v00 = __shfl_sync(0xffffffffu, s[ks][0], src0);
            float v01 = __shfl_sync(0xffffffffu, s[ks][1], src0);
            float v20 = __shfl_sync(0xffffffffu, s[ks][2], src0);
            float v21 = __shfl_sync(0xffffffffu, s[ks][3], src0);
            float v0b = __shfl_sync(0xffffffffu, s[ks][0], src1);
            float v1b = __shfl_sync(0xffffffffu, s[ks][1], src1);
            float v2b = __shfl_sync(0xffffffffu, s[ks][2], src1);
            float v3b = __shfl_sync(0xffffffffu, s[ks][3], src1);
            uint32_t a[4];
            a[0] = f2tf32(oddl ? v01 : v00);
            a[1] = f2tf32(oddl ? v21 : v20);
            a[2] = f2tf32(oddl ? v1b : v0b);
            a[3] = f2tf32(oddl ? v3b : v2b);
            const int vr0 = (ks * 8 + lk) * SA;
            const int vr1 = (ks * 8 + lk + 4) * SA;
#pragma unroll
            for (int j = 0; j < 8; j++) {
                const int dcol = j * 8 + (lane >> 2);
                uint32_t b[2];
                b[0] = cV[vr0 + dcol];
                b[1] = cV[vr1 + dcol];
                MMA_TF32(o[j], a, b);
            }
        }
    }
#undef KV_ISSUE

    // Epilogue -> g_att [B,T,C], tf32 pre-rounded (proj stages with no cvt)
    const float inv0 = 1.f / l0, inv1 = 1.f / l1;
    const int b = bh >> 4, h = bh & 15;
    const int gr0 = q0 + r0w, gr1 = gr0 + 8;
    float* o0 = g_att + ((size_t)(b * TLEN + gr0)) * CDIM + h * HD;
    float* o1 = g_att + ((size_t)(b * TLEN + gr1)) * CDIM + h * HD;
#pragma unroll
    for (int j = 0; j < 8; j++) {
        const int c = j * 8 + 2 * lk;
        *(float2*)(o0 + c) = make_float2(__uint_as_float(f2tf32(o[j][0] * inv0)),
                                         __uint_as_float(f2tf32(o[j][1] * inv0)));
        *(float2*)(o1 + c) = make_float2(__uint_as_float(f2tf32(o[j][2] * inv1)),
                                         __uint_as_float(f2tf32(o[j][3] * inv1)));
    }
}

// ---------------------------------------------------------------------------
extern "C" void kernel_launch(void* const* d_in, const int* in_sizes, int n_in,
                              void* d_out, int out_size) {
    const float* x = (const float*)d_in[0];
    const float* W_qkv = (const float*)d_in[1];
    const float* b_qkv = (const float*)d_in[2];
    const float* W_proj = (const float*)d_in[3];
    const float* b_proj = (const float*)d_in[4];
    float* out = (float*)d_out;

    float *xr = nullptr, *wqkvT = nullptr, *wprojT = nullptr, *attp = nullptr;
    cudaGetSymbolAddress((void**)&xr, g_xr);
    cudaGetSymbolAddress((void**)&wqkvT, g_WqkvT);
    cudaGetSymbolAddress((void**)&wprojT, g_WprojT);
    cudaGetSymbolAddress((void**)&attp, g_att);

    cudaFuncSetAttribute(attn_mma, cudaFuncAttributeMaxDynamicSharedMemorySize,
                         ATTN_SMEM);
    cudaFuncSetAttribute(mm_tf32<0>, cudaFuncAttributeMaxDynamicSharedMemorySize,
                         MM_SMEM);
    cudaFuncSetAttribute(mm_tf32<1>, cudaFuncAttributeMaxDynamicSharedMemorySize,
                         MM_SMEM);

    round_x<<<2048, 256>>>(x, xr, BT * CDIM / 4);
    transpose32<<<dim3(N3 / 32, CDIM / 32), 256>>>(W_qkv, wqkvT, CDIM, N3);
    transpose32<<<dim3(CDIM / 32, CDIM / 32), 256>>>(W_proj, wprojT, CDIM, CDIM);

    mm_tf32<0><<<dim3(N3 / 128, BT / 128), 256, MM_SMEM>>>(
        xr, wqkvT, b_qkv, nullptr);

    attn_mma<<<dim3(TLEN / 64, BSZ * NH), 128, ATTN_SMEM>>>();

    mm_tf32<1><<<dim3(CDIM / 128, BT / 128), 256, MM_SMEM>>>(
        attp, wprojT, b_proj, out);
}

// round 16
// speedup vs baseline: 1.1235x; 1.0010x over previous
#include <cuda_runtime.h>
#include <cstdint>
#include <math.h>

#define BSZ 4
#define TLEN 2048
#define CDIM 1024
#define NH 16
#define HD 64
#define BT (BSZ * TLEN)      /* 8192 */
#define N3 (3 * CDIM)        /* 3072 */

// Scratch (allocation-free rule: __device__ globals)
__device__ float g_xr[BT * CDIM];     // x, tf32-rounded bits
__device__ float g_Q[BT * CDIM];      // [B,H,T,Dh] tf32-rounded
__device__ float g_K[BT * CDIM];      // tf32-rounded
__device__ float g_V[BT * CDIM];      // tf32-rounded
__device__ float g_att[BT * CDIM];    // [B,T,C] tf32-rounded
__device__ float g_WqkvT[N3 * CDIM];  // W_qkv^T, tf32-rounded
__device__ float g_WprojT[CDIM * CDIM]; // W_proj^T, tf32-rounded

// ---------------------------------------------------------------------------
// Portable helpers (sm_80+ — no 'a'-suffix features)
// ---------------------------------------------------------------------------
__device__ __forceinline__ uint32_t f2tf32(float x) {
    uint32_t u;
    asm("cvt.rna.tf32.f32 %0, %1;" : "=r"(u) : "f"(x));
    return u;
}
__device__ __forceinline__ uint32_t smem_u32(const void* p) {
    uint32_t a;
    asm("{ .reg .u64 t; cvta.to.shared.u64 t, %1; cvt.u32.u64 %0, t; }"
        : "=r"(a) : "l"(p));
    return a;
}

#define MMA_TF32(d, a, b)                                                        \
    asm volatile(                                                                \
        "mma.sync.aligned.m16n8k8.row.col.f32.tf32.tf32.f32 "                    \
        "{%0,%1,%2,%3}, {%4,%5,%6,%7}, {%8,%9}, {%0,%1,%2,%3};"                  \
        : "+f"((d)[0]), "+f"((d)[1]), "+f"((d)[2]), "+f"((d)[3])                 \
        : "r"((a)[0]), "r"((a)[1]), "r"((a)[2]), "r"((a)[3]),                    \
          "r"((b)[0]), "r"((b)[1]))

#define CP_ASYNC16(smaddr, gptr)                                                 \
    asm volatile("cp.async.cg.shared.global [%0], [%1], 16;"                     \
                 :: "r"(smaddr), "l"(gptr))
#define CP_COMMIT()    asm volatile("cp.async.commit_group;" ::: "memory")
#define CP_WAIT_ALL()  asm volatile("cp.async.wait_group 0;" ::: "memory")
#define CP_WAIT_ONE()  asm volatile("cp.async.wait_group 1;" ::: "memory")

// ---------------------------------------------------------------------------
// One-shot input pre-round: out[i] = rna(in[i])  (tf32 bits in fp32 storage)
// ---------------------------------------------------------------------------
__global__ __launch_bounds__(256) void round_x(const float* __restrict__ in,
                                               float* __restrict__ out, int n4) {
    const int stride = gridDim.x * blockDim.x;
    for (int i = blockIdx.x * blockDim.x + threadIdx.x; i < n4; i += stride) {
        float4 v = ((const float4*)in)[i];
        uint4 u;
        u.x = f2tf32(v.x); u.y = f2tf32(v.y);
        u.z = f2tf32(v.z); u.w = f2tf32(v.w);
        ((uint4*)out)[i] = u;
    }
}

// ---------------------------------------------------------------------------
// One-shot weight transposes + tf32 pre-round: out[N,K] = rna(in[K,N]^T).
// ---------------------------------------------------------------------------
__global__ __launch_bounds__(256) void transpose32(const float* __restrict__ in,
                                                   float* __restrict__ out,
                                                   int R, int C) {
    __shared__ float tile[32][33];
    const int c0 = blockIdx.x * 32, r0 = blockIdx.y * 32;
    const int tx = threadIdx.x & 31, ty = threadIdx.x >> 5;
#pragma unroll
    for (int i = 0; i < 4; i++) {
        int r = ty + i * 8;
        tile[r][tx] = in[(size_t)(r0 + r) * C + c0 + tx];
    }
    __syncthreads();
#pragma unroll
    for (int i = 0; i < 4; i++) {
        int r = ty + i * 8;
        out[(size_t)(c0 + r) * R + r0 + tx] =
            __uint_as_float(f2tf32(tile[tx][r]));
    }
}

// ---------------------------------------------------------------------------
// tf32 mma.sync GEMM, cp.async 3-STAGE pipeline, ONE barrier per K chunk.
// Loads for chunk ch+2 issue after barrier(ch): ~2 compute phases to land.
// wait_group 1 (except last chunk). All inputs pre-rounded -> pure copy.
// MODE 0: QKV scatter (rounded); MODE 1: plain out.
// ---------------------------------------------------------------------------
#define SSTR 36
#define MMT (128 * SSTR)
#define MM_SMEM (6 * MMT * 4)

template <int MODE>
__global__ __launch_bounds__(256, 2)
void mm_tf32(const float* __restrict__ A, const float* __restrict__ Bt,
             const float* __restrict__ bias, float* __restrict__ out) {
    extern __shared__ uint32_t gsm[];   // [A0|B0|A1|B1|A2|B2]
    const uint32_t smb = smem_u32(gsm);

    const int t = threadIdx.x;
    const int m0 = blockIdx.y * 128;
    const int n0 = blockIdx.x * 128;
    const int lane = t & 31, w = t >> 5;
    const int wr = w >> 2, wc = w & 3;

    float d[4][4][4];
#pragma unroll
    for (int i = 0; i < 4; i++)
#pragma unroll
        for (int j = 0; j < 4; j++)
#pragma unroll
            for (int e = 0; e < 4; e++) d[i][j][e] = 0.f;

    const int gr = t >> 3;
    const int gc4 = (t & 7) * 4;
    const float* Ap = A + (size_t)(m0 + gr) * CDIM + gc4;
    const float* Bp = Bt + (size_t)(n0 + gr) * CDIM + gc4;

    const int ar = wr * 64 + (lane >> 2);
    const int ac = lane & 3;
    const int br = wc * 32 + (lane >> 2);

#define MMISS(ch)                                                                \
    do {                                                                         \
        const int _k0 = (ch) * 32, _st = (ch) % 3;                               \
        const uint32_t _ab = smb + (uint32_t)(_st * 2 * MMT) * 4u;               \
        const uint32_t _bb = _ab + (uint32_t)MMT * 4u;                           \
        _Pragma("unroll")                                                        \
        for (int p = 0; p < 4; p++) {                                            \
            const uint32_t off = ((gr + p * 32) * SSTR + gc4) * 4u;              \
            CP_ASYNC16(_ab + off, Ap + (size_t)(p * 32) * CDIM + _k0);           \
            CP_ASYNC16(_bb + off, Bp + (size_t)(p * 32) * CDIM + _k0);           \
        }                                                                        \
        CP_COMMIT();                                                             \
    } while (0)

    MMISS(0);
    MMISS(1);

    for (int ch = 0; ch < 32; ch++) {
        uint32_t* As = gsm + (ch % 3) * 2 * MMT;
        uint32_t* Bs = As + MMT;

        if (ch == 31) CP_WAIT_ALL(); else CP_WAIT_ONE();  // chunk ch arrived
        __syncthreads();   // all warps past compute(ch-1); buffer (ch+2)%3 free
        if (ch < 30) MMISS(ch + 2);  // lands during compute(ch), compute(ch+1)

#pragma unroll
        for (int ks = 0; ks < 4; ks++) {
            const int kk = ks * 8 + ac;
            uint32_t a[4][4], b[4][2];
#pragma unroll
            for (int i = 0; i < 4; i++) {
                const int r = (ar + i * 16) * SSTR;
                a[i][0] = As[r + kk];
                a[i][1] = As[r + 8 * SSTR + kk];
                a[i][2] = As[r + kk + 4];
                a[i][3] = As[r + 8 * SSTR + kk + 4];
            }
#pragma unroll
            for (int j = 0; j < 4; j++) {
                const int r = (br + j * 8) * SSTR;
                b[j][0] = Bs[r + kk];
                b[j][1] = Bs[r + kk + 4];
            }
#pragma unroll
            for (int i = 0; i < 4; i++)
#pragma unroll
                for (int j = 0; j < 4; j++) MMA_TF32(d[i][j], a[i], b[j]);
        }
    }
#undef MMISS

    const int r0 = lane >> 2, c0 = (lane & 3) * 2;
#pragma unroll
    for (int i = 0; i < 4; i++) {
        const int gmA = m0 + wr * 64 + i * 16 + r0;
        const int gmB = gmA + 8;
#pragma unroll
        for (int j = 0; j < 4; j++) {
            const int gn = n0 + wc * 32 + j * 8 + c0;
            const float bx = bias[gn], by = bias[gn + 1];
            if (MODE == 0) {
                float2 vA = make_float2(
                    __uint_as_float(f2tf32(d[i][j][0] + bx)),
                    __uint_as_float(f2tf32(d[i][j][1] + by)));
                float2 vB = make_float2(
                    __uint_as_float(f2tf32(d[i][j][2] + bx)),
                    __uint_as_float(f2tf32(d[i][j][3] + by)));
                const int which = gn >> 10;
                const int c = gn & 1023;
                const int h = c >> 6, d0 = c & 63;
                float* base = (which == 0) ? g_Q : ((which == 1) ? g_K : g_V);
                const int bA = gmA >> 11, tA = gmA & 2047;
                const int bB = gmB >> 11, tB = gmB & 2047;
                *(float2*)(base + ((size_t)(bA * NH + h) * TLEN + tA) * HD + d0) = vA;
                *(float2*)(base + ((size_t)(bB * NH + h) * TLEN + tB) * HD + d0) = vB;
            } else {
                float2 vA = make_float2(d[i][j][0] + bx, d[i][j][1] + by);
                float2 vB = make_float2(d[i][j][2] + bx, d[i][j][3] + by);
                *(float2*)(out + (size_t)gmA * CDIM + gn) = vA;
                *(float2*)(out + (size_t)gmB * CDIM + gn) = vB;
            }
        }
    }
}

// ---------------------------------------------------------------------------
// Tensor-core flash attention v10 (causal, tf32 mma.sync) — EXACT R15.
// K/V pre-rounded cp.async 2-stage; Q frags in registers; P via shfl.
// ---------------------------------------------------------------------------
#define SA 68
#define ATILE (64 * SA)
#define ATTN_SMEM (4 * ATILE * 4)

__global__ __launch_bounds__(128) void attn_mma() {
    extern __shared__ uint32_t smw[];   // [Ks0 | Ks1 | Vs0 | Vs1]
    const uint32_t smb = smem_u32(smw);

    const int t = threadIdx.x;
    const int lane = t & 31, w = t >> 5;
    const int qi = (gridDim.x - 1) - blockIdx.x;  // heavy tiles first
    const int bh = blockIdx.y;
    const int q0 = qi * 64;

    const float* Qg = g_Q + (size_t)bh * TLEN * HD;
    const float* Kg = g_K + (size_t)bh * TLEN * HD;
    const float* Vg = g_V + (size_t)bh * TLEN * HD;

    const int r0w = w * 16 + (lane >> 2);
    const int abase = r0w * SA;
    const int lk = lane & 3;
    const int src0 = (lane & 28) + ((lane >> 1) & 1);
    const int src1 = src0 + 2;
    const bool oddl = lane & 1;

#define KV_ISSUE(kt)                                                             \
    do {                                                                         \
        const int _k0 = (kt) * 64, _st = (kt) & 1;                               \
        const uint32_t _kb = smb + (_st ? (uint32_t)ATILE : 0u) * 4u;            \
        const uint32_t _vb = smb + ((_st ? 3u : 2u) * ATILE) * 4u;               \
        _Pragma("unroll")                                                        \
        for (int it = 0; it < 8; it++) {                                         \
            const int i = it * 128 + t;                                          \
            const int row = i >> 4, c4 = (i & 15) * 4;                           \
            const uint32_t off = (row * SA + c4) * 4u;                           \
            CP_ASYNC16(_kb + off, Kg + (size_t)(_k0 + row) * HD + c4);           \
            CP_ASYNC16(_vb + off, Vg + (size_t)(_k0 + row) * HD + c4);           \
        }                                                                        \
        CP_COMMIT();                                                             \
    } while (0)

    KV_ISSUE(0);   // tile 0 -> stage 0, in flight during Q staging

    // Stage Q through Ks stage-1 buffer (free until tile 1 is issued).
    {
        uint32_t* Qs = smw + ATILE;
        float4 qv[8];
#pragma unroll
        for (int it = 0; it < 8; it++) {
            const int i = it * 128 + t;
            qv[it] = *(const float4*)(Qg + (size_t)(q0 + (i >> 4)) * HD +
                                      (i & 15) * 4);
        }
#pragma unroll
        for (int it = 0; it < 8; it++) {
            const int i = it * 128 + t;
            const int row = i >> 4, c4 = (i & 15) * 4;
            uint4 u;  // Q pre-rounded; *0.125 (2^-3) is exact
            u.x = __float_as_uint(qv[it].x * 0.125f);
            u.y = __float_as_uint(qv[it].y * 0.125f);
            u.z = __float_as_uint(qv[it].z * 0.125f);
            u.w = __float_as_uint(qv[it].w * 0.125f);
            *(uint4*)&Qs[row * SA + c4] = u;
        }
    }
    __syncthreads();
    uint32_t qf[8][4];
    {
        uint32_t* Qs = smw + ATILE;
#pragma unroll
        for (int ks = 0; ks < 8; ks++) {
            const int kk = ks * 8 + lk;
            qf[ks][0] = Qs[abase + kk];
            qf[ks][1] = Qs[abase + 8 * SA + kk];
            qf[ks][2] = Qs[abase + kk + 4];
            qf[ks][3] = Qs[abase + 8 * SA + kk + 4];
        }
    }

    float o[8][4];
#pragma unroll
    for (int j = 0; j < 8; j++)
#pragma unroll
        for (int e = 0; e < 4; e++) o[j][e] = 0.f;
    float m0 = -1e30f, m1 = -1e30f, l0 = 0.f, l1 = 0.f;

    for (int kt = 0; kt <= qi; kt++) {
        const int k0 = kt * 64;
        uint32_t* cK = smw + (kt & 1) * ATILE;
        uint32_t* cV = smw + (2 + (kt & 1)) * ATILE;

        CP_WAIT_ALL();        // tile kt arrived
        __syncthreads();      // + qf loads done (kt=0) / compute(kt-1) done
        if (kt < qi) KV_ISSUE(kt + 1);   // overlaps compute(kt)

        // S = (Q*scale) @ K^T   (Q from registers)
        float s[8][4];
#pragma unroll
        for (int j = 0; j < 8; j++)
#pragma unroll
            for (int e = 0; e < 4; e++) s[j][e] = 0.f;
#pragma unroll
        for (int ks = 0; ks < 8; ks++) {
            const int kk = ks * 8 + lk;
#pragma unroll
            for (int j = 0; j < 8; j++) {
                const int r = (j * 8 + (lane >> 2)) * SA;
                uint32_t b[2];
                b[0] = cK[r + kk];
                b[1] = cK[r + kk + 4];
                MMA_TF32(s[j], qf[ks], b);
            }
        }

        // Causal mask (diagonal tile only; uniform branch)
        if (kt == qi) {
            const int gr0 = q0 + r0w, gr1 = gr0 + 8;
#pragma unroll
            for (int j = 0; j < 8; j++) {
                const int c = k0 + j * 8 + 2 * lk;
                if (c > gr0) s[j][0] = -1e30f;
                if (c + 1 > gr0) s[j][1] = -1e30f;
                if (c > gr1) s[j][2] = -1e30f;
                if (c + 1 > gr1) s[j][3] = -1e30f;
            }
        }

        // Online softmax: rows r0w (c0,c1) and r0w+8 (c2,c3)
        float tm0 = -1e30f, tm1 = -1e30f;
#pragma unroll
        for (int j = 0; j < 8; j++) {
            tm0 = fmaxf(tm0, fmaxf(s[j][0], s[j][1]));
            tm1 = fmaxf(tm1, fmaxf(s[j][2], s[j][3]));
        }
        tm0 = fmaxf(tm0, __shfl_xor_sync(0xffffffffu, tm0, 1));
        tm0 = fmaxf(tm0, __shfl_xor_sync(0xffffffffu, tm0, 2));
        tm1 = fmaxf(tm1, __shfl_xor_sync(0xffffffffu, tm1, 1));
        tm1 = fmaxf(tm1, __shfl_xor_sync(0xffffffffu, tm1, 2));

        const float mn0 = fmaxf(m0, tm0), mn1 = fmaxf(m1, tm1);
        const float al0 = __expf(m0 - mn0), al1 = __expf(m1 - mn1);
        m0 = mn0; m1 = mn1;

        float rs0 = 0.f, rs1 = 0.f;
#pragma unroll
        for (int j = 0; j < 8; j++) {
            s[j][0] = __expf(s[j][0] - mn0); rs0 += s[j][0];
            s[j][1] = __expf(s[j][1] - mn0); rs0 += s[j][1];
            s[j][2] = __expf(s[j][2] - mn1); rs1 += s[j][2];
            s[j][3] = __expf(s[j][3] - mn1); rs1 += s[j][3];
        }
        rs0 += __shfl_xor_sync(0xffffffffu, rs0, 1);
        rs0 += __shfl_xor_sync(0xffffffffu, rs0, 2);
        rs1 += __shfl_xor_sync(0xffffffffu, rs1, 1);
        rs1 += __shfl_xor_sync(0xffffffffu, rs1, 2);
        l0 = l0 * al0 + rs0;
        l1 = l1 * al1 + rs1;
#pragma unroll
        for (int j = 0; j < 8; j++) {
            o[j][0] *= al0; o[j][1] *= al0;
            o[j][2] *= al1; o[j][3] *= al1;
        }

        // O += P @ V. P A-frags from s C-frags via in-register permute.
#pragma unroll
        for (int ks = 0; ks < 8; ks++) {
            float v00 = __shfl_sync(0xffffffffu, s[ks][0], src0);
            float v01 = __shfl_sync(0xffffffffu, s[ks][1], src0);
            float v20 = __shfl_sync(0xffffffffu, s[ks][2], src0);
            float v21 = __shfl_sync(0xffffffffu, s[ks][3], src0);
            float v0b = __shfl_sync(0xffffffffu, s[ks][0], src1);
            float v1b = __shfl_sync(0xffffffffu, s[ks][1], src1);
            float v2b = __shfl_sync(0xffffffffu, s[ks][2], src1);
            float v3b = __shfl_sync(0xffffffffu, s[ks][3], src1);
            uint32_t a[4];
            a[0] = f2tf32(oddl ? v01 : v00);
            a[1] = f2tf32(oddl ? v21 : v20);
            a[2] = f2tf32(oddl ? v1b : v0b);
            a[3] = f2tf32(oddl ? v3b : v2b);
            const int vr0 = (ks * 8 + lk) * SA;
            const int vr1 = (ks * 8 + lk + 4) * SA;
#pragma unroll
            for (int j = 0; j < 8; j++) {
                const int dcol = j * 8 + (lane >> 2);
                uint32_t b[2];
                b[0] = cV[vr0 + dcol];
                b[1] = cV[vr1 + dcol];
                MMA_TF32(o[j], a, b);
            }
        }
    }
#undef KV_ISSUE

    // Epilogue -> g_att [B,T,C], tf32 pre-rounded (proj stages with no cvt)
    const float inv0 = 1.f / l0, inv1 = 1.f / l1;
    const int b = bh >> 4, h = bh & 15;
    const int gr0 = q0 + r0w, gr1 = gr0 + 8;
    float* o0 = g_att + ((size_t)(b * TLEN + gr0)) * CDIM + h * HD;
    float* o1 = g_att + ((size_t)(b * TLEN + gr1)) * CDIM + h * HD;
#pragma unroll
    for (int j = 0; j < 8; j++) {
        const int c = j * 8 + 2 * lk;
        *(float2*)(o0 + c) = make_float2(__uint_as_float(f2tf32(o[j][0] * inv0)),
                                         __uint_as_float(f2tf32(o[j][1] * inv0)));
        *(float2*)(o1 + c) = make_float2(__uint_as_float(f2tf32(o[j][2] * inv1)),
                                         __uint_as_float(f2tf32(o[j][3] * inv1)));
    }
}

// ---------------------------------------------------------------------------
extern "C" void kernel_launch(void* const* d_in, const int* in_sizes, int n_in,
                              void* d_out, int out_size) {
    const float* x = (const float*)d_in[0];
    const float* W_qkv = (const float*)d_in[1];
    const float* b_qkv = (const float*)d_in[2];
    const float* W_proj = (const float*)d_in[3];
    const float* b_proj = (const float*)d_in[4];
    float* out = (float*)d_out;

    float *xr = nullptr, *wqkvT = nullptr, *wprojT = nullptr, *attp = nullptr;
    cudaGetSymbolAddress((void**)&xr, g_xr);
    cudaGetSymbolAddress((void**)&wqkvT, g_WqkvT);
    cudaGetSymbolAddress((void**)&wprojT, g_WprojT);
    cudaGetSymbolAddress((void**)&attp, g_att);

    cudaFuncSetAttribute(attn_mma, cudaFuncAttributeMaxDynamicSharedMemorySize,
                         ATTN_SMEM);
    cudaFuncSetAttribute(mm_tf32<0>, cudaFuncAttributeMaxDynamicSharedMemorySize,
                         MM_SMEM);
    cudaFuncSetAttribute(mm_tf32<1>, cudaFuncAttributeMaxDynamicSharedMemorySize,
                         MM_SMEM);

    round_x<<<2048, 256>>>(x, xr, BT * CDIM / 4);
    transpose32<<<dim3(N3 / 32, CDIM / 32), 256>>>(W_qkv, wqkvT, CDIM, N3);
    transpose32<<<dim3(CDIM / 32, CDIM / 32), 256>>>(W_proj, wprojT, CDIM, CDIM);

    mm_tf32<0><<<dim3(N3 / 128, BT / 128), 256, MM_SMEM>>>(
        xr, wqkvT, b_qkv, nullptr);

    attn_mma<<<dim3(TLEN / 64, BSZ * NH), 128, ATTN_SMEM>>>();

    mm_tf32<1><<<dim3(CDIM / 128, BT / 128), 256, MM_SMEM>>>(
        attp, wprojT, b_proj, out);
}

// round 17
// speedup vs baseline: 1.1432x; 1.0176x over previous
#include <cuda_runtime.h>
#include <cstdint>
#include <math.h>

#define BSZ 4
#define TLEN 2048
#define CDIM 1024
#define NH 16
#define HD 64
#define BT (BSZ * TLEN)      /* 8192 */
#define N3 (3 * CDIM)        /* 3072 */

// Scratch (allocation-free rule: __device__ globals)
__device__ float g_xr[BT * CDIM];     // x, tf32-rounded bits
__device__ float g_Q[BT * CDIM];      // [B,H,T,Dh] tf32-rounded
__device__ float g_K[BT * CDIM];      // tf32-rounded
__device__ float g_V[BT * CDIM];      // tf32-rounded
__device__ float g_att[BT * CDIM];    // [B,T,C] tf32-rounded
__device__ float g_WqkvT[N3 * CDIM];  // W_qkv^T, tf32-rounded
__device__ float g_WprojT[CDIM * CDIM]; // W_proj^T, tf32-rounded

// ---------------------------------------------------------------------------
// Portable helpers (sm_80+ — no 'a'-suffix features)
// ---------------------------------------------------------------------------
__device__ __forceinline__ uint32_t f2tf32(float x) {
    uint32_t u;
    asm("cvt.rna.tf32.f32 %0, %1;" : "=r"(u) : "f"(x));
    return u;
}
__device__ __forceinline__ uint32_t smem_u32(const void* p) {
    uint32_t a;
    asm("{ .reg .u64 t; cvta.to.shared.u64 t, %1; cvt.u32.u64 %0, t; }"
        : "=r"(a) : "l"(p));
    return a;
}

#define MMA_TF32(d, a, b)                                                        \
    asm volatile(                                                                \
        "mma.sync.aligned.m16n8k8.row.col.f32.tf32.tf32.f32 "                    \
        "{%0,%1,%2,%3}, {%4,%5,%6,%7}, {%8,%9}, {%0,%1,%2,%3};"                  \
        : "+f"((d)[0]), "+f"((d)[1]), "+f"((d)[2]), "+f"((d)[3])                 \
        : "r"((a)[0]), "r"((a)[1]), "r"((a)[2]), "r"((a)[3]),                    \
          "r"((b)[0]), "r"((b)[1]))

#define CP_ASYNC16(smaddr, gptr)                                                 \
    asm volatile("cp.async.cg.shared.global [%0], [%1], 16;"                     \
                 :: "r"(smaddr), "l"(gptr))
#define CP_COMMIT()    asm volatile("cp.async.commit_group;" ::: "memory")
#define CP_WAIT_ALL()  asm volatile("cp.async.wait_group 0;" ::: "memory")
#define CP_WAIT_ONE()  asm volatile("cp.async.wait_group 1;" ::: "memory")

// ---------------------------------------------------------------------------
// One-shot input pre-round: out[i] = rna(in[i])  (tf32 bits in fp32 storage)
// ---------------------------------------------------------------------------
__global__ __launch_bounds__(256) void round_x(const float* __restrict__ in,
                                               float* __restrict__ out, int n4) {
    const int stride = gridDim.x * blockDim.x;
    for (int i = blockIdx.x * blockDim.x + threadIdx.x; i < n4; i += stride) {
        float4 v = ((const float4*)in)[i];
        uint4 u;
        u.x = f2tf32(v.x); u.y = f2tf32(v.y);
        u.z = f2tf32(v.z); u.w = f2tf32(v.w);
        ((uint4*)out)[i] = u;
    }
}

// ---------------------------------------------------------------------------
// One-shot weight transposes + tf32 pre-round: out[N,K] = rna(in[K,N]^T).
// ---------------------------------------------------------------------------
__global__ __launch_bounds__(256) void transpose32(const float* __restrict__ in,
                                                   float* __restrict__ out,
                                                   int R, int C) {
    __shared__ float tile[32][33];
    const int c0 = blockIdx.x * 32, r0 = blockIdx.y * 32;
    const int tx = threadIdx.x & 31, ty = threadIdx.x >> 5;
#pragma unroll
    for (int i = 0; i < 4; i++) {
        int r = ty + i * 8;
        tile[r][tx] = in[(size_t)(r0 + r) * C + c0 + tx];
    }
    __syncthreads();
#pragma unroll
    for (int i = 0; i < 4; i++) {
        int r = ty + i * 8;
        out[(size_t)(c0 + r) * R + r0 + tx] =
            __uint_as_float(f2tf32(tile[tx][r]));
    }
}

// ---------------------------------------------------------------------------
// tf32 mma.sync GEMM v2: 128 threads / 4 warps, warp grid 2x2, warp tile
// 64x64 (8 n-frags) -> smem crossbar bytes per MMA drop 48B -> 32B.
// cp.async 3-stage pipeline, ONE barrier per K chunk, inputs pre-rounded.
// Accumulation order per output element unchanged -> bit-exact.
// MODE 0: QKV scatter (rounded); MODE 1: plain out.
// ---------------------------------------------------------------------------
#define SSTR 36
#define MMT (128 * SSTR)
#define MM_SMEM (6 * MMT * 4)

template <int MODE>
__global__ __launch_bounds__(128)
void mm_tf32(const float* __restrict__ A, const float* __restrict__ Bt,
             const float* __restrict__ bias, float* __restrict__ out) {
    extern __shared__ uint32_t gsm[];   // [A0|B0|A1|B1|A2|B2]
    const uint32_t smb = smem_u32(gsm);

    const int t = threadIdx.x;
    const int m0 = blockIdx.y * 128;
    const int n0 = blockIdx.x * 128;
    const int lane = t & 31, w = t >> 5;
    const int wr = w >> 1, wc = w & 1;      // warp grid 2x2

    float d[4][8][4];
#pragma unroll
    for (int i = 0; i < 4; i++)
#pragma unroll
        for (int j = 0; j < 8; j++)
#pragma unroll
            for (int e = 0; e < 4; e++) d[i][j][e] = 0.f;

    const int gr = t >> 3;             // 0..15
    const int gc4 = (t & 7) * 4;
    const float* Ap = A + (size_t)(m0 + gr) * CDIM + gc4;
    const float* Bp = Bt + (size_t)(n0 + gr) * CDIM + gc4;

    const int ar = wr * 64 + (lane >> 2);
    const int ac = lane & 3;
    const int brb = wc * 64 + (lane >> 2);

#define MMISS(ch)                                                                \
    do {                                                                         \
        const int _k0 = (ch) * 32, _st = (ch) % 3;                               \
        const uint32_t _ab = smb + (uint32_t)(_st * 2 * MMT) * 4u;               \
        const uint32_t _bb = _ab + (uint32_t)MMT * 4u;                           \
        _Pragma("unroll")                                                        \
        for (int p = 0; p < 8; p++) {                                            \
            const uint32_t off = ((gr + p * 16) * SSTR + gc4) * 4u;              \
            CP_ASYNC16(_ab + off, Ap + (size_t)(p * 16) * CDIM + _k0);           \
            CP_ASYNC16(_bb + off, Bp + (size_t)(p * 16) * CDIM + _k0);           \
        }                                                                        \
        CP_COMMIT();                                                             \
    } while (0)

    MMISS(0);
    MMISS(1);

    for (int ch = 0; ch < 32; ch++) {
        uint32_t* As = gsm + (ch % 3) * 2 * MMT;
        uint32_t* Bs = As + MMT;

        if (ch == 31) CP_WAIT_ALL(); else CP_WAIT_ONE();  // chunk ch arrived
        __syncthreads();   // all warps past compute(ch-1); buffer (ch+2)%3 free
        if (ch < 30) MMISS(ch + 2);  // lands during compute(ch..ch+1)

#pragma unroll
        for (int ks = 0; ks < 4; ks++) {
            const int kk = ks * 8 + ac;
            uint32_t a[4][4], b[8][2];
#pragma unroll
            for (int i = 0; i < 4; i++) {
                const int r = (ar + i * 16) * SSTR;
                a[i][0] = As[r + kk];
                a[i][1] = As[r + 8 * SSTR + kk];
                a[i][2] = As[r + kk + 4];
                a[i][3] = As[r + 8 * SSTR + kk + 4];
            }
#pragma unroll
            for (int j = 0; j < 8; j++) {
                const int r = (brb + j * 8) * SSTR;
                b[j][0] = Bs[r + kk];
                b[j][1] = Bs[r + kk + 4];
            }
#pragma unroll
            for (int i = 0; i < 4; i++)
#pragma unroll
                for (int j = 0; j < 8; j++) MMA_TF32(d[i][j], a[i], b[j]);
        }
    }
#undef MMISS

    const int r0 = lane >> 2, c0 = (lane & 3) * 2;
#pragma unroll
    for (int i = 0; i < 4; i++) {
        const int gmA = m0 + wr * 64 + i * 16 + r0;
        const int gmB = gmA + 8;
#pragma unroll
        for (int j = 0; j < 8; j++) {
            const int gn = n0 + wc * 64 + j * 8 + c0;
            const float bx = bias[gn], by = bias[gn + 1];
            if (MODE == 0) {
                float2 vA = make_float2(
                    __uint_as_float(f2tf32(d[i][j][0] + bx)),
                    __uint_as_float(f2tf32(d[i][j][1] + by)));
                float2 vB = make_float2(
                    __uint_as_float(f2tf32(d[i][j][2] + bx)),
                    __uint_as_float(f2tf32(d[i][j][3] + by)));
                const int which = gn >> 10;
                const int c = gn & 1023;
                const int h = c >> 6, d0 = c & 63;
                float* base = (which == 0) ? g_Q : ((which == 1) ? g_K : g_V);
                const int bA = gmA >> 11, tA = gmA & 2047;
                const int bB = gmB >> 11, tB = gmB & 2047;
                *(float2*)(base + ((size_t)(bA * NH + h) * TLEN + tA) * HD + d0) = vA;
                *(float2*)(base + ((size_t)(bB * NH + h) * TLEN + tB) * HD + d0) = vB;
            } else {
                float2 vA = make_float2(d[i][j][0] + bx, d[i][j][1] + by);
                float2 vB = make_float2(d[i][j][2] + bx, d[i][j][3] + by);
                *(float2*)(out + (size_t)gmA * CDIM + gn) = vA;
                *(float2*)(out + (size_t)gmB * CDIM + gn) = vB;
            }
        }
    }
}

// ---------------------------------------------------------------------------
// Tensor-core flash attention v10 (causal, tf32 mma.sync) — EXACT R15.
// K/V pre-rounded cp.async 2-stage; Q frags in registers; P via shfl.
// ---------------------------------------------------------------------------
#define SA 68
#define ATILE (64 * SA)
#define ATTN_SMEM (4 * ATILE * 4)

__global__ __launch_bounds__(128) void attn_mma() {
    extern __shared__ uint32_t smw[];   // [Ks0 | Ks1 | Vs0 | Vs1]
    const uint32_t smb = smem_u32(smw);

    const int t = threadIdx.x;
    const int lane = t & 31, w = t >> 5;
    const int qi = (gridDim.x - 1) - blockIdx.x;  // heavy tiles first
    const int bh = blockIdx.y;
    const int q0 = qi * 64;

    const float* Qg = g_Q + (size_t)bh * TLEN * HD;
    const float* Kg = g_K + (size_t)bh * TLEN * HD;
    const float* Vg = g_V + (size_t)bh * TLEN * HD;

    const int r0w = w * 16 + (lane >> 2);
    const int abase = r0w * SA;
    const int lk = lane & 3;
    const int src0 = (lane & 28) + ((lane >> 1) & 1);
    const int src1 = src0 + 2;
    const bool oddl = lane & 1;

#define KV_ISSUE(kt)                                                             \
    do {                                                                         \
        const int _k0 = (kt) * 64, _st = (kt) & 1;                               \
        const uint32_t _kb = smb + (_st ? (uint32_t)ATILE : 0u) * 4u;            \
        const uint32_t _vb = smb + ((_st ? 3u : 2u) * ATILE) * 4u;               \
        _Pragma("unroll")                                                        \
        for (int it = 0; it < 8; it++) {                                         \
            const int i = it * 128 + t;                                          \
            const int row = i >> 4, c4 = (i & 15) * 4;                           \
            const uint32_t off = (row * SA + c4) * 4u;                           \
            CP_ASYNC16(_kb + off, Kg + (size_t)(_k0 + row) * HD + c4);           \
            CP_ASYNC16(_vb + off, Vg + (size_t)(_k0 + row) * HD + c4);           \
        }                                                                        \
        CP_COMMIT();                                                             \
    } while (0)

    KV_ISSUE(0);   // tile 0 -> stage 0, in flight during Q staging

    // Stage Q through Ks stage-1 buffer (free until tile 1 is issued).
    {
        uint32_t* Qs = smw + ATILE;
        float4 qv[8];
#pragma unroll
        for (int it = 0; it < 8; it++) {
            const int i = it * 128 + t;
            qv[it] = *(const float4*)(Qg + (size_t)(q0 + (i >> 4)) * HD +
                                      (i & 15) * 4);
        }
#pragma unroll
        for (int it = 0; it < 8; it++) {
            const int i = it * 128 + t;
            const int row = i >> 4, c4 = (i & 15) * 4;
            uint4 u;  // Q pre-rounded; *0.125 (2^-3) is exact
            u.x = __float_as_uint(qv[it].x * 0.125f);
            u.y = __float_as_uint(qv[it].y * 0.125f);
            u.z = __float_as_uint(qv[it].z * 0.125f);
            u.w = __float_as_uint(qv[it].w * 0.125f);
            *(uint4*)&Qs[row * SA + c4] = u;
        }
    }
    __syncthreads();
    uint32_t qf[8][4];
    {
        uint32_t* Qs = smw + ATILE;
#pragma unroll
        for (int ks = 0; ks < 8; ks++) {
            const int kk = ks * 8 + lk;
            qf[ks][0] = Qs[abase + kk];
            qf[ks][1] = Qs[abase + 8 * SA + kk];
            qf[ks][2] = Qs[abase + kk + 4];
            qf[ks][3] = Qs[abase + 8 * SA + kk + 4];
        }
    }

    float o[8][4];
#pragma unroll
    for (int j = 0; j < 8; j++)
#pragma unroll
        for (int e = 0; e < 4; e++) o[j][e] = 0.f;
    float m0 = -1e30f, m1 = -1e30f, l0 = 0.f, l1 = 0.f;

    for (int kt = 0; kt <= qi; kt++) {
        const int k0 = kt * 64;
        uint32_t* cK = smw + (kt & 1) * ATILE;
        uint32_t* cV = smw + (2 + (kt & 1)) * ATILE;

        CP_WAIT_ALL();        // tile kt arrived
        __syncthreads();      // + qf loads done (kt=0) / compute(kt-1) done
        if (kt < qi) KV_ISSUE(kt + 1);   // overlaps compute(kt)

        // S = (Q*scale) @ K^T   (Q from registers)
        float s[8][4];
#pragma unroll
        for (int j = 0; j < 8; j++)
#pragma unroll
            for (int e = 0; e < 4; e++) s[j][e] = 0.f;
#pragma unroll
        for (int ks = 0; ks < 8; ks++) {
            const int kk = ks * 8 + lk;
#pragma unroll
            for (int j = 0; j < 8; j++) {
                const int r = (j * 8 + (lane >> 2)) * SA;
                uint32_t b[2];
                b[0] = cK[r + kk];
                b[1] = cK[r + kk + 4];
                MMA_TF32(s[j], qf[ks], b);
            }
        }

        // Causal mask (diagonal tile only; uniform branch)
        if (kt == qi) {
            const int gr0 = q0 + r0w, gr1 = gr0 + 8;
#pragma unroll
            for (int j = 0; j < 8; j++) {
                const int c = k0 + j * 8 + 2 * lk;
                if (c > gr0) s[j][0] = -1e30f;
                if (c + 1 > gr0) s[j][1] = -1e30f;
                if (c > gr1) s[j][2] = -1e30f;
                if (c + 1 > gr1) s[j][3] = -1e30f;
            }
        }

        // Online softmax: rows r0w (c0,c1) and r0w+8 (c2,c3)
        float tm0 = -1e30f, tm1 = -1e30f;
#pragma unroll
        for (int j = 0; j < 8; j++) {
            tm0 = fmaxf(tm0, fmaxf(s[j][0], s[j][1]));
            tm1 = fmaxf(tm1, fmaxf(s[j][2], s[j][3]));
        }
        tm0 = fmaxf(tm0, __shfl_xor_sync(0xffffffffu, tm0, 1));
        tm0 = fmaxf(tm0, __shfl_xor_sync(0xffffffffu, tm0, 2));
        tm1 = fmaxf(tm1, __shfl_xor_sync(0xffffffffu, tm1, 1));
        tm1 = fmaxf(tm1, __shfl_xor_sync(0xffffffffu, tm1, 2));

        const float mn0 = fmaxf(m0, tm0), mn1 = fmaxf(m1, tm1);
        const float al0 = __expf(m0 - mn0), al1 = __expf(m1 - mn1);
        m0 = mn0; m1 = mn1;

        float rs0 = 0.f, rs1 = 0.f;
#pragma unroll
        for (int j = 0; j < 8; j++) {
            s[j][0] = __expf(s[j][0] - mn0); rs0 += s[j][0];
            s[j][1] = __expf(s[j][1] - mn0); rs0 += s[j][1];
            s[j][2] = __expf(s[j][2] - mn1); rs1 += s[j][2];
            s[j][3] = __expf(s[j][3] - mn1); rs1 += s[j][3];
        }
        rs0 += __shfl_xor_sync(0xffffffffu, rs0, 1);
        rs0 += __shfl_xor_sync(0xffffffffu, rs0, 2);
        rs1 += __shfl_xor_sync(0xffffffffu, rs1, 1);
        rs1 += __shfl_xor_sync(0xffffffffu, rs1, 2);
        l0 = l0 * al0 + rs0;
        l1 = l1 * al1 + rs1;
#pragma unroll
        for (int j = 0; j < 8; j++) {
            o[j][0] *= al0; o[j][1] *= al0;
            o[j][2] *= al1; o[j][3] *= al1;
        }

        // O += P @ V. P A-frags from s C-frags via in-register permute.
#pragma unroll
        for (int ks = 0; ks < 8; ks++) {
            float v00 = __shfl_sync(0xffffffffu, s[ks][0], src0);
            float v01 = __shfl_sync(0xffffffffu, s[ks][1], src0);
            float v20 = __shfl_sync(0xffffffffu, s[ks][2], src0);
            float v21 = __shfl_sync(0xffffffffu, s[ks][3], src0);
            float v0b = __shfl_sync(0xffffffffu, s[ks][0], src1);
            float v1b = __shfl_sync(0xffffffffu, s[ks][1], src1);
            float v2b = __shfl_sync(0xffffffffu, s[ks][2], src1);
            float v3b = __shfl_sync(0xffffffffu, s[ks][3], src1);
            uint32_t a[4];
            a[0] = f2tf32(oddl ? v01 : v00);
            a[1] = f2tf32(oddl ? v21 : v20);
            a[2] = f2tf32(oddl ? v1b : v0b);
            a[3] = f2tf32(oddl ? v3b : v2b);
            const int vr0 = (ks * 8 + lk) * SA;
            const int vr1 = (ks * 8 + lk + 4) * SA;
#pragma unroll
            for (int j = 0; j < 8; j++) {
                const int dcol = j * 8 + (lane >> 2);
                uint32_t b[2];
                b[0] = cV[vr0 + dcol];
                b[1] = cV[vr1 + dcol];
                MMA_TF32(o[j], a, b);
            }
        }
    }
#undef KV_ISSUE

    // Epilogue -> g_att [B,T,C], tf32 pre-rounded (proj stages with no cvt)
    const float inv0 = 1.f / l0, inv1 = 1.f / l1;
    const int b = bh >> 4, h = bh & 15;
    const int gr0 = q0 + r0w, gr1 = gr0 + 8;
    float* o0 = g_att + ((size_t)(b * TLEN + gr0)) * CDIM + h * HD;
    float* o1 = g_att + ((size_t)(b * TLEN + gr1)) * CDIM + h * HD;
#pragma unroll
    for (int j = 0; j < 8; j++) {
        const int c = j * 8 + 2 * lk;
        *(float2*)(o0 + c) = make_float2(__uint_as_float(f2tf32(o[j][0] * inv0)),
                                         __uint_as_float(f2tf32(o[j][1] * inv0)));
        *(float2*)(o1 + c) = make_float2(__uint_as_float(f2tf32(o[j][2] * inv1)),
                                         __uint_as_float(f2tf32(o[j][3] * inv1)));
    }
}

// ---------------------------------------------------------------------------
extern "C" void kernel_launch(void* const* d_in, const int* in_sizes, int n_in,
                              void* d_out, int out_size) {
    const float* x = (const float*)d_in[0];
    const float* W_qkv = (const float*)d_in[1];
    const float* b_qkv = (const float*)d_in[2];
    const float* W_proj = (const float*)d_in[3];
    const float* b_proj = (const float*)d_in[4];
    float* out = (float*)d_out;

    float *xr = nullptr, *wqkvT = nullptr, *wprojT = nullptr, *attp = nullptr;
    cudaGetSymbolAddress((void**)&xr, g_xr);
    cudaGetSymbolAddress((void**)&wqkvT, g_WqkvT);
    cudaGetSymbolAddress((void**)&wprojT, g_WprojT);
    cudaGetSymbolAddress((void**)&attp, g_att);

    cudaFuncSetAttribute(attn_mma, cudaFuncAttributeMaxDynamicSharedMemorySize,
                         ATTN_SMEM);
    cudaFuncSetAttribute(mm_tf32<0>, cudaFuncAttributeMaxDynamicSharedMemorySize,
                         MM_SMEM);
    cudaFuncSetAttribute(mm_tf32<1>, cudaFuncAttributeMaxDynamicSharedMemorySize,
                         MM_SMEM);

    round_x<<<2048, 256>>>(x, xr, BT * CDIM / 4);
    transpose32<<<dim3(N3 / 32, CDIM / 32), 256>>>(W_qkv, wqkvT, CDIM, N3);
    transpose32<<<dim3(CDIM / 32, CDIM / 32), 256>>>(W_proj, wprojT, CDIM, CDIM);

    mm_tf32<0><<<dim3(N3 / 128, BT / 128), 128, MM_SMEM>>>(
        xr, wqkvT, b_qkv, nullptr);

    attn_mma<<<dim3(TLEN / 64, BSZ * NH), 128, ATTN_SMEM>>>();

    mm_tf32<1><<<dim3(CDIM / 128, BT / 128), 128, MM_SMEM>>>(
        attp, wprojT, b_proj, out);
}